// round 11
// baseline (speedup 1.0000x reference)
#include <cuda_runtime.h>
#include <cuda_fp16.h>
#include <cstdint>

// ============================================================================
// FactoredCausalSelfAttention  (B=2, T=2048, C=1024, H=16, D=64)
// Round 11: gemm mainloop restructured: 3-stage cp.async pipeline with ONE
//           __syncthreads per iteration + XOR-swizzled smem (no padding).
//           attn = round-10 exact (64-row CTAs, 2 CTAs/SM).
// ============================================================================

#define B_   2
#define T_   2048
#define C_   1024
#define H_   16
#define D_   64
#define BH_  (B_*H_)
#define M_GEMM (B_*T_)      // 4096
#define N_GEMM (2*C_)       // 2048
#define K_GEMM (C_)         // 1024

// ---- device scratch ----
__device__ __align__(16) __half g_Xh [(size_t)M_GEMM*K_GEMM];
__device__ __align__(16) __half g_Xl [(size_t)M_GEMM*K_GEMM];
__device__ __align__(16) __half g_Whi[(size_t)N_GEMM*K_GEMM];  // [n][k]
__device__ __align__(16) __half g_Wlo[(size_t)N_GEMM*K_GEMM];  // [n][k]
__device__ __align__(16) __half g_qh [(size_t)BH_*T_*D_];      // [bh][t][d]
__device__ __align__(16) __half g_ql [(size_t)BH_*T_*D_];
__device__ __align__(16) __half g_kh [(size_t)BH_*T_*D_];
__device__ __align__(16) __half g_kl [(size_t)BH_*T_*D_];
__device__ __align__(16) __half g_vh [(size_t)BH_*D_*T_];      // [bh][d][t]
__device__ __align__(16) __half g_vl [(size_t)BH_*D_*T_];

// ---------------------------------------------------------------- helpers ---
__device__ __forceinline__ void mma_fp16(float c[4], const uint32_t a[4],
                                         uint32_t b0, uint32_t b1)
{
    asm volatile(
        "mma.sync.aligned.m16n8k16.row.col.f32.f16.f16.f32 "
        "{%0,%1,%2,%3}, {%4,%5,%6,%7}, {%8,%9}, {%0,%1,%2,%3};\n"
        : "+f"(c[0]), "+f"(c[1]), "+f"(c[2]), "+f"(c[3])
        : "r"(a[0]), "r"(a[1]), "r"(a[2]), "r"(a[3]), "r"(b0), "r"(b1));
}

__device__ __forceinline__ void ldsm_x4(uint32_t r[4], uint32_t addr)
{
    asm volatile("ldmatrix.sync.aligned.m8n8.x4.shared.b16 {%0,%1,%2,%3}, [%4];"
                 : "=r"(r[0]), "=r"(r[1]), "=r"(r[2]), "=r"(r[3]) : "r"(addr));
}

__device__ __forceinline__ float ex2f(float x) {
    float y;
    asm("ex2.approx.f32 %0, %1;" : "=f"(y) : "f"(x));
    return y;
}

__device__ __forceinline__ void cp_async16(uint32_t smem_addr, const void* gptr) {
    asm volatile("cp.async.ca.shared.global [%0], [%1], 16;\n"
                 :: "r"(smem_addr), "l"(gptr));
}
__device__ __forceinline__ void cp_async_commit() {
    asm volatile("cp.async.commit_group;\n");
}
template<int N>
__device__ __forceinline__ void cp_async_wait() {
    asm volatile("cp.async.wait_group %0;\n" :: "n"(N));
}

// 64-byte-row XOR swizzle: 16B-chunk column permuted by row pairs.
// byte offset for (row, chunk) in a [rows][32 halves] array:
__device__ __forceinline__ uint32_t swz64(int row, int chunk) {
    return (uint32_t)(row * 64 + ((chunk ^ ((row >> 1) & 3)) << 4));
}

// ----------------------------------------------------------------------------
// prep kernels (unchanged)
// ----------------------------------------------------------------------------
__global__ __launch_bounds__(256) void prep_x_kernel(const float* __restrict__ X)
{
    int i = blockIdx.x * 256 + threadIdx.x;
    float2 v = ((const float2*)X)[i];
    __half h0 = __float2half_rn(v.x);
    __half h1 = __float2half_rn(v.y);
    ((__half2*)g_Xh)[i] = __halves2half2(h0, h1);
    ((__half2*)g_Xl)[i] = __halves2half2(__float2half_rn(v.x - __half2float(h0)),
                                         __float2half_rn(v.y - __half2float(h1)));
}

__global__ __launch_bounds__(256) void prep_w_kernel(const float* __restrict__ W)
{
    __shared__ float t[32][33];
    const int bn = blockIdx.x, bk = blockIdx.y;
    const int tx = threadIdx.x, ty = threadIdx.y;
    #pragma unroll
    for (int j = 0; j < 4; j++)
        t[ty + 8*j][tx] = W[(size_t)(bk*32 + ty + 8*j) * N_GEMM + bn*32 + tx];
    __syncthreads();
    #pragma unroll
    for (int j = 0; j < 4; j++) {
        const int n = bn*32 + ty + 8*j;
        const int k = bk*32 + tx;
        float v = t[tx][ty + 8*j];
        __half h = __float2half_rn(v);
        g_Whi[(size_t)n * K_GEMM + k] = h;
        g_Wlo[(size_t)n * K_GEMM + k] = __float2half_rn(v - __half2float(h));
    }
}

__global__ __launch_bounds__(256) void prep_v_kernel(const float* __restrict__ xt)
{
    __shared__ float t[32][33];
    const int bh = blockIdx.z;
    const int b = bh >> 4, h = bh & 15;
    const int tt = blockIdx.x * 32;
    const int dd = blockIdx.y * 32;
    const int tx = threadIdx.x, ty = threadIdx.y;
    #pragma unroll
    for (int j = 0; j < 4; j++)
        t[ty + 8*j][tx] = xt[(size_t)(b*T_ + tt + ty + 8*j) * C_ + h*D_ + dd + tx];
    __syncthreads();
    #pragma unroll
    for (int j = 0; j < 4; j++) {
        const int d = dd + ty + 8*j;
        float v = t[tx][ty + 8*j];
        __half hh = __float2half_rn(v);
        const size_t o = ((size_t)bh*D_ + d) * T_ + tt + tx;
        g_vh[o] = hh;
        g_vl[o] = __float2half_rn(v - __half2float(hh));
    }
}

// ----------------------------------------------------------------------------
// GEMM (fp16 3-pass): qk = X @ W + bias -> split-scatter q/k hi/lo fp16
// CTA 128x128, BK=32, 8 warps. 3-stage cp.async pipeline, 1 sync/iteration,
// XOR-swizzled smem ([128 rows][32 halves] per array, 8KB; 4 arrays/stage).
// ----------------------------------------------------------------------------
#define G_ARR_B   8192                    // bytes per array (128*64B rows)
#define G_STAGE_B (4*G_ARR_B)             // 32768
#define G_NSTAGE  3
#define GEMM_SMEM_BYTES (G_NSTAGE*G_STAGE_B)   // 98304

__global__ __launch_bounds__(256, 2) void gemm_qk_kernel(const float* __restrict__ bias)
{
    extern __shared__ __half gsm[];
    const uint32_t smb = (uint32_t)__cvta_generic_to_shared(gsm);

    const int bx = blockIdx.x;
    const int by = blockIdx.y;
    const int tid = threadIdx.x;
    const int warp = tid >> 5;
    const int lane = tid & 31;
    const int lr = lane >> 2;
    const int lc = lane & 3;
    const int wm = warp >> 1;
    const int wn = warp & 1;

    // ldmatrix row/chunk patterns
    const int aRow = (lane & 15);            // + tile base row
    const int aChk = (lane >> 4);            // + 2*ks
    const int bRow = ((lane >> 4) << 3) + (lane & 7);
    const int bChk = ((lane >> 3) & 1);      // + 2*ks

    float c[2][8][4];
    #pragma unroll
    for (int mt = 0; mt < 2; mt++)
        #pragma unroll
        for (int nt = 0; nt < 8; nt++)
            #pragma unroll
            for (int j = 0; j < 4; j++) c[mt][nt][j] = 0.f;

    auto issue_stage = [&](int stage, int k0) {
        const uint32_t st = smb + (uint32_t)(stage * G_STAGE_B);
        #pragma unroll
        for (int i = 0; i < 8; i++) {
            int idx = tid + i * 256;          // 0..2047 16B chunks
            int sec = idx >> 9;               // 0:Ah 1:Al 2:Bh 3:Bl
            int sub = idx & 511;
            int r   = sub >> 2;               // 0..127
            int ch  = sub & 3;                // 16B chunk in row
            const __half* src;
            if      (sec == 0) src = g_Xh  + (size_t)(by*128 + r) * K_GEMM + k0 + ch*8;
            else if (sec == 1) src = g_Xl  + (size_t)(by*128 + r) * K_GEMM + k0 + ch*8;
            else if (sec == 2) src = g_Whi + (size_t)(bx*128 + r) * K_GEMM + k0 + ch*8;
            else               src = g_Wlo + (size_t)(bx*128 + r) * K_GEMM + k0 + ch*8;
            cp_async16(st + (uint32_t)sec * G_ARR_B + swz64(r, ch), src);
        }
        cp_async_commit();
    };

    issue_stage(0, 0);
    issue_stage(1, 32);

    const int NIT = K_GEMM / 32;   // 32
    for (int it = 0; it < NIT; it++) {
        if (it + 1 < NIT) {
            cp_async_wait<1>();    // stage it complete (it+1 may be in flight)
        } else {
            cp_async_wait<0>();
        }
        __syncthreads();           // also: all warps done computing stage it-1
        if (it + 2 < NIT) issue_stage((it + 2) % G_NSTAGE, (it + 2) * 32);

        const uint32_t Ah = smb + (uint32_t)((it % G_NSTAGE) * G_STAGE_B);
        const uint32_t Al = Ah + G_ARR_B;
        const uint32_t Bh = Ah + 2 * G_ARR_B;
        const uint32_t Bl = Ah + 3 * G_ARR_B;

        #pragma unroll
        for (int ks = 0; ks < 2; ks++) {
            uint32_t ah[2][4], al[2][4];
            #pragma unroll
            for (int mt = 0; mt < 2; mt++) {
                const uint32_t ao = swz64(wm*32 + mt*16 + aRow, 2*ks + aChk);
                ldsm_x4(ah[mt], Ah + ao);
                ldsm_x4(al[mt], Al + ao);
            }
            #pragma unroll
            for (int ntp = 0; ntp < 4; ntp++) {
                const uint32_t bo = swz64(wn*64 + ntp*16 + bRow, 2*ks + bChk);
                uint32_t bh4[4], bl4[4];
                ldsm_x4(bh4, Bh + bo);
                ldsm_x4(bl4, Bl + bo);
                #pragma unroll
                for (int half = 0; half < 2; half++)
                    #pragma unroll
                    for (int mt = 0; mt < 2; mt++)
                        mma_fp16(c[mt][2*ntp+half], ah[mt], bh4[2*half], bh4[2*half+1]);
                #pragma unroll
                for (int half = 0; half < 2; half++)
                    #pragma unroll
                    for (int mt = 0; mt < 2; mt++)
                        mma_fp16(c[mt][2*ntp+half], ah[mt], bl4[2*half], bl4[2*half+1]);
                #pragma unroll
                for (int half = 0; half < 2; half++)
                    #pragma unroll
                    for (int mt = 0; mt < 2; mt++)
                        mma_fp16(c[mt][2*ntp+half], al[mt], bh4[2*half], bh4[2*half+1]);
            }
        }
        // no trailing sync: next iteration's top sync protects this stage
    }

    #pragma unroll
    for (int mt = 0; mt < 2; mt++) {
        #pragma unroll
        for (int rr = 0; rr < 2; rr++) {
            const int m = by*128 + wm*32 + mt*16 + rr*8 + lr;
            const int b = m >> 11;
            const int t = m & (T_ - 1);
            #pragma unroll
            for (int nt = 0; nt < 8; nt++) {
                const int n0 = bx*128 + wn*64 + nt*8 + 2*lc;
                const float v0 = c[mt][nt][rr*2 + 0] + bias[n0];
                const float v1 = c[mt][nt][rr*2 + 1] + bias[n0 + 1];
                __half h0 = __float2half_rn(v0);
                __half h1 = __float2half_rn(v1);
                __half l0 = __float2half_rn(v0 - __half2float(h0));
                __half l1 = __float2half_rn(v1 - __half2float(h1));
                if (n0 < C_) {
                    const int hh = n0 >> 6, d = n0 & 63;
                    const size_t o = (((size_t)(b*H_ + hh)) * T_ + t) * D_ + d;
                    *(__half2*)&g_qh[o] = __halves2half2(h0, h1);
                    *(__half2*)&g_ql[o] = __halves2half2(l0, l1);
                } else {
                    const int n2 = n0 - C_;
                    const int hh = n2 >> 6, d = n2 & 63;
                    const size_t o = (((size_t)(b*H_ + hh)) * T_ + t) * D_ + d;
                    *(__half2*)&g_kh[o] = __halves2half2(h0, h1);
                    *(__half2*)&g_kl[o] = __halves2half2(l0, l1);
                }
            }
        }
    }
}

// ----------------------------------------------------------------------------
// Flash attention (round-10 exact): 128 threads / 64 q-rows per CTA,
// fp16 3-pass QK^T and PV, cp.async double-buffered KV, 2 CTAs/SM.
// ----------------------------------------------------------------------------
#define A_STAGE 36864
#define A_PQ    73728
#define ATTN_SMEM_BYTES 92160
#define A_THREADS 128

__global__ __launch_bounds__(A_THREADS) void attn_kernel(float* __restrict__ out)
{
    extern __shared__ char smraw[];
    const uint32_t sm_base = (uint32_t)__cvta_generic_to_shared(smraw);
    __half* Ph  = (__half*)(smraw + A_PQ);
    __half* Pl  = Ph + 64*72;
    const uint32_t PhU = sm_base + A_PQ;
    const uint32_t PlU = PhU + 64*72*2;

    const int bh = blockIdx.y;
    const int b  = bh >> 4;
    const int h  = bh & 15;
    const int tid  = threadIdx.x;
    const int warp = tid >> 5;
    const int lane = tid & 31;
    const int lr = lane >> 2;
    const int lc = lane & 3;
    const int qt = gridDim.x - 1 - blockIdx.x;
    const int t0 = qt * 64;

    const int aRow = (lane & 15);
    const int aCol = (lane >> 4) * 8;
    const int bRow = ((lane >> 4) << 3) + (lane & 7);
    const int bCol = ((lane >> 3) & 1) * 8;

    {
        __half* Qhs = Ph;
        __half* Qls = Pl;
        #pragma unroll
        for (int i = 0; i < 4; i++) {
            int idx = tid + i * A_THREADS;
            int r = idx >> 3, c8 = (idx & 7) * 8;
            *(float4*)&Qhs[r*72 + c8] =
                *(const float4*)(g_qh + ((size_t)bh*T_ + t0 + r)*D_ + c8);
            *(float4*)&Qls[r*72 + c8] =
                *(const float4*)(g_ql + ((size_t)bh*T_ + t0 + r)*D_ + c8);
        }
    }
    __syncthreads();

    uint32_t qfh[4][4], qfl[4][4];
    #pragma unroll
    for (int ks = 0; ks < 4; ks++) {
        const uint32_t qo = (uint32_t)(((warp*16 + aRow) * 72) + 16*ks + aCol) * 2;
        ldsm_x4(qfh[ks], PhU + qo);
        ldsm_x4(qfl[ks], PlU + qo);
    }
    __syncthreads();

    float o[8][4];
    #pragma unroll
    for (int dt = 0; dt < 8; dt++)
        #pragma unroll
        for (int j = 0; j < 4; j++) o[dt][j] = 0.f;

    float m0 = -1e30f, m1 = -1e30f;
    float l0 = 0.f, l1 = 0.f;
    const float C2 = 0.125f * 1.44269504089f;

    const int rg0 = t0 + warp*16 + lr;
    const int rg1 = rg0 + 8;
    const int prow0 = (warp*16 + lr) * 72;
    const int prow1 = prow0 + 8*72;

    auto issue_tile = [&](int stage, int j0) {
        const uint32_t st = sm_base + (uint32_t)stage * A_STAGE;
        #pragma unroll
        for (int i = 0; i < 16; i++) {
            int idx = tid + i * A_THREADS;
            int sec = idx >> 9;
            int sub = idx & 511;
            int r   = sub >> 3;
            int c8  = (sub & 7) * 8;
            const __half* src;
            if      (sec == 0) src = g_kh + ((size_t)bh*T_ + j0 + r)*D_ + c8;
            else if (sec == 1) src = g_kl + ((size_t)bh*T_ + j0 + r)*D_ + c8;
            else if (sec == 2) src = g_vh + ((size_t)bh*D_ + r)*T_ + j0 + c8;
            else               src = g_vl + ((size_t)bh*D_ + r)*T_ + j0 + c8;
            cp_async16(st + (uint32_t)(sec * 9216) + (uint32_t)(r*72 + c8)*2, src);
        }
        cp_async_commit();
    };

    const int ntiles = qt + 1;
    issue_tile(0, 0);

    for (int it = 0; it < ntiles; it++) {
        const int j0 = it * 64;
        if (it + 1 < ntiles) {
            issue_tile((it + 1) & 1, (it + 1) * 64);
            cp_async_wait<1>();
        } else {
            cp_async_wait<0>();
        }
        __syncthreads();

        const uint32_t KhiU = sm_base + (uint32_t)((it & 1) * A_STAGE);
        const uint32_t KloU = KhiU + 9216;
        const uint32_t VhU  = KhiU + 2*9216;
        const uint32_t VlU  = KhiU + 3*9216;

        float s[8][4];
        #pragma unroll
        for (int nt = 0; nt < 8; nt++)
            #pragma unroll
            for (int j = 0; j < 4; j++) s[nt][j] = 0.f;

        #pragma unroll
        for (int ks = 0; ks < 4; ks++) {
            #pragma unroll
            for (int ntp = 0; ntp < 4; ntp++) {
                const uint32_t ko =
                    (uint32_t)(((ntp*16 + bRow) * 72) + 16*ks + bCol) * 2;
                uint32_t kh4[4], kl4[4];
                ldsm_x4(kh4, KhiU + ko);
                ldsm_x4(kl4, KloU + ko);
                #pragma unroll
                for (int half = 0; half < 2; half++) {
                    const int nt = 2*ntp + half;
                    mma_fp16(s[nt], qfh[ks], kh4[2*half], kh4[2*half+1]);
                    mma_fp16(s[nt], qfh[ks], kl4[2*half], kl4[2*half+1]);
                    mma_fp16(s[nt], qfl[ks], kh4[2*half], kh4[2*half+1]);
                }
            }
        }

        if (j0 + 63 > t0) {
            #pragma unroll
            for (int nt = 0; nt < 8; nt++) {
                int cg = j0 + nt*8 + 2*lc;
                if (cg     > rg0) s[nt][0] = -1e30f;
                if (cg + 1 > rg0) s[nt][1] = -1e30f;
                if (cg     > rg1) s[nt][2] = -1e30f;
                if (cg + 1 > rg1) s[nt][3] = -1e30f;
            }
        }

        float t0m = -1e30f, t1m = -1e30f;
        #pragma unroll
        for (int nt = 0; nt < 8; nt++) {
            t0m = fmaxf(t0m, fmaxf(s[nt][0], s[nt][1]));
            t1m = fmaxf(t1m, fmaxf(s[nt][2], s[nt][3]));
        }
        t0m = fmaxf(t0m, __shfl_xor_sync(0xffffffffu, t0m, 1));
        t0m = fmaxf(t0m, __shfl_xor_sync(0xffffffffu, t0m, 2));
        t1m = fmaxf(t1m, __shfl_xor_sync(0xffffffffu, t1m, 1));
        t1m = fmaxf(t1m, __shfl_xor_sync(0xffffffffu, t1m, 2));

        const float mn0 = fmaxf(m0, t0m);
        const float mn1 = fmaxf(m1, t1m);
        const float a0 = ex2f((m0 - mn0) * C2);
        const float a1 = ex2f((m1 - mn1) * C2);
        m0 = mn0; m1 = mn1;
        l0 *= a0; l1 *= a1;
        #pragma unroll
        for (int dt = 0; dt < 8; dt++) {
            o[dt][0] *= a0; o[dt][1] *= a0;
            o[dt][2] *= a1; o[dt][3] *= a1;
        }

        #pragma unroll
        for (int nt = 0; nt < 8; nt++) {
            float p0 = ex2f((s[nt][0] - m0) * C2);
            float p1 = ex2f((s[nt][1] - m0) * C2);
            float p2 = ex2f((s[nt][2] - m1) * C2);
            float p3 = ex2f((s[nt][3] - m1) * C2);
            l0 += p0 + p1;
            l1 += p2 + p3;
            __half h0 = __float2half_rn(p0), h1 = __float2half_rn(p1);
            __half h2 = __float2half_rn(p2), h3 = __float2half_rn(p3);
            *(__half2*)&Ph[prow0 + nt*8 + 2*lc] = __halves2half2(h0, h1);
            *(__half2*)&Ph[prow1 + nt*8 + 2*lc] = __halves2half2(h2, h3);
            *(__half2*)&Pl[prow0 + nt*8 + 2*lc] =
                __halves2half2(__float2half_rn(p0 - __half2float(h0)),
                               __float2half_rn(p1 - __half2float(h1)));
            *(__half2*)&Pl[prow1 + nt*8 + 2*lc] =
                __halves2half2(__float2half_rn(p2 - __half2float(h2)),
                               __float2half_rn(p3 - __half2float(h3)));
        }
        __syncwarp();

        #pragma unroll
        for (int ks = 0; ks < 4; ks++) {
            uint32_t pah[4], pal[4];
            const uint32_t po =
                (uint32_t)(((warp*16 + aRow) * 72) + 16*ks + aCol) * 2;
            ldsm_x4(pah, PhU + po);
            ldsm_x4(pal, PlU + po);
            #pragma unroll
            for (int dtp = 0; dtp < 4; dtp++) {
                const uint32_t vo =
                    (uint32_t)(((dtp*16 + bRow) * 72) + 16*ks + bCol) * 2;
                uint32_t vh4[4], vl4[4];
                ldsm_x4(vh4, VhU + vo);
                ldsm_x4(vl4, VlU + vo);
                #pragma unroll
                for (int half = 0; half < 2; half++) {
                    const int dt = 2*dtp + half;
                    mma_fp16(o[dt], pah, vh4[2*half], vh4[2*half+1]);
                    mma_fp16(o[dt], pah, vl4[2*half], vl4[2*half+1]);
                    mma_fp16(o[dt], pal, vh4[2*half], vh4[2*half+1]);
                }
            }
        }
        __syncthreads();
    }

    l0 += __shfl_xor_sync(0xffffffffu, l0, 1);
    l0 += __shfl_xor_sync(0xffffffffu, l0, 2);
    l1 += __shfl_xor_sync(0xffffffffu, l1, 1);
    l1 += __shfl_xor_sync(0xffffffffu, l1, 2);
    const float inv0 = 1.f / l0;
    const float inv1 = 1.f / l1;

    float* out0 = out + ((size_t)(b*T_ + rg0))*C_ + h*D_;
    float* out1 = out + ((size_t)(b*T_ + rg1))*C_ + h*D_;
    #pragma unroll
    for (int dt = 0; dt < 8; dt++) {
        *(float2*)(out0 + dt*8 + 2*lc) = make_float2(o[dt][0]*inv0, o[dt][1]*inv0);
        *(float2*)(out1 + dt*8 + 2*lc) = make_float2(o[dt][2]*inv1, o[dt][3]*inv1);
    }
}

// ----------------------------------------------------------------------------
extern "C" void kernel_launch(void* const* d_in, const int* in_sizes, int n_in,
                              void* d_out, int out_size)
{
    const float* x_norm = (const float*)d_in[0];
    const float* xt_cur = (const float*)d_in[1];
    const float* W_attn = (const float*)d_in[2];
    const float* b_attn = (const float*)d_in[3];
    float* out = (float*)d_out;

    cudaFuncSetAttribute(gemm_qk_kernel,
                         cudaFuncAttributeMaxDynamicSharedMemorySize, GEMM_SMEM_BYTES);
    cudaFuncSetAttribute(attn_kernel,
                         cudaFuncAttributeMaxDynamicSharedMemorySize, ATTN_SMEM_BYTES);

    prep_x_kernel<<<(M_GEMM*K_GEMM/2)/256, 256>>>(x_norm);
    prep_w_kernel<<<dim3(N_GEMM/32, K_GEMM/32), dim3(32, 8)>>>(W_attn);
    prep_v_kernel<<<dim3(T_/32, D_/32, BH_), dim3(32, 8)>>>(xt_cur);

    dim3 g1(N_GEMM/128, M_GEMM/128);   // (16, 32)
    gemm_qk_kernel<<<g1, 256, GEMM_SMEM_BYTES>>>(b_attn);

    dim3 g2(T_/64, B_*H_);             // (32, 32)
    attn_kernel<<<g2, A_THREADS, ATTN_SMEM_BYTES>>>(out);
}

// round 12
// speedup vs baseline: 1.1465x; 1.1465x over previous
#include <cuda_runtime.h>
#include <cuda_fp16.h>
#include <cstdint>

// ============================================================================
// FactoredCausalSelfAttention  (B=2, T=2048, C=1024, H=16, D=64)
// Round 12: gemm cut to 2-pass fp16 split (Xh*Whi + Xh*Wlo; Xl term dropped,
//           predicted rel_err ~3e-4 < 1e-3). Round-7 gemm skeleton, 3 smem
//           arrays/stage. Attn = round-10 exact (3-pass, 64-row CTAs).
// ============================================================================

#define B_   2
#define T_   2048
#define C_   1024
#define H_   16
#define D_   64
#define BH_  (B_*H_)
#define M_GEMM (B_*T_)      // 4096
#define N_GEMM (2*C_)       // 2048
#define K_GEMM (C_)         // 1024

// ---- device scratch ----
__device__ __align__(16) __half g_Xh [(size_t)M_GEMM*K_GEMM];
__device__ __align__(16) __half g_Whi[(size_t)N_GEMM*K_GEMM];  // [n][k]
__device__ __align__(16) __half g_Wlo[(size_t)N_GEMM*K_GEMM];  // [n][k]
__device__ __align__(16) __half g_qh [(size_t)BH_*T_*D_];      // [bh][t][d]
__device__ __align__(16) __half g_ql [(size_t)BH_*T_*D_];
__device__ __align__(16) __half g_kh [(size_t)BH_*T_*D_];
__device__ __align__(16) __half g_kl [(size_t)BH_*T_*D_];
__device__ __align__(16) __half g_vh [(size_t)BH_*D_*T_];      // [bh][d][t]
__device__ __align__(16) __half g_vl [(size_t)BH_*D_*T_];

// ---------------------------------------------------------------- helpers ---
__device__ __forceinline__ void mma_fp16(float c[4], const uint32_t a[4],
                                         uint32_t b0, uint32_t b1)
{
    asm volatile(
        "mma.sync.aligned.m16n8k16.row.col.f32.f16.f16.f32 "
        "{%0,%1,%2,%3}, {%4,%5,%6,%7}, {%8,%9}, {%0,%1,%2,%3};\n"
        : "+f"(c[0]), "+f"(c[1]), "+f"(c[2]), "+f"(c[3])
        : "r"(a[0]), "r"(a[1]), "r"(a[2]), "r"(a[3]), "r"(b0), "r"(b1));
}

__device__ __forceinline__ void ldsm_x4(uint32_t r[4], uint32_t addr)
{
    asm volatile("ldmatrix.sync.aligned.m8n8.x4.shared.b16 {%0,%1,%2,%3}, [%4];"
                 : "=r"(r[0]), "=r"(r[1]), "=r"(r[2]), "=r"(r[3]) : "r"(addr));
}

__device__ __forceinline__ float ex2f(float x) {
    float y;
    asm("ex2.approx.f32 %0, %1;" : "=f"(y) : "f"(x));
    return y;
}

__device__ __forceinline__ void cp_async16(uint32_t smem_addr, const void* gptr) {
    asm volatile("cp.async.ca.shared.global [%0], [%1], 16;\n"
                 :: "r"(smem_addr), "l"(gptr));
}
__device__ __forceinline__ void cp_async_commit() {
    asm volatile("cp.async.commit_group;\n");
}
template<int N>
__device__ __forceinline__ void cp_async_wait() {
    asm volatile("cp.async.wait_group %0;\n" :: "n"(N));
}

// ----------------------------------------------------------------------------
// prep kernels
// ----------------------------------------------------------------------------
__global__ __launch_bounds__(256) void prep_x_kernel(const float* __restrict__ X)
{
    int i = blockIdx.x * 256 + threadIdx.x;
    float2 v = ((const float2*)X)[i];
    ((__half2*)g_Xh)[i] = __halves2half2(__float2half_rn(v.x), __float2half_rn(v.y));
}

__global__ __launch_bounds__(256) void prep_w_kernel(const float* __restrict__ W)
{
    __shared__ float t[32][33];
    const int bn = blockIdx.x, bk = blockIdx.y;
    const int tx = threadIdx.x, ty = threadIdx.y;
    #pragma unroll
    for (int j = 0; j < 4; j++)
        t[ty + 8*j][tx] = W[(size_t)(bk*32 + ty + 8*j) * N_GEMM + bn*32 + tx];
    __syncthreads();
    #pragma unroll
    for (int j = 0; j < 4; j++) {
        const int n = bn*32 + ty + 8*j;
        const int k = bk*32 + tx;
        float v = t[tx][ty + 8*j];
        __half h = __float2half_rn(v);
        g_Whi[(size_t)n * K_GEMM + k] = h;
        g_Wlo[(size_t)n * K_GEMM + k] = __float2half_rn(v - __half2float(h));
    }
}

__global__ __launch_bounds__(256) void prep_v_kernel(const float* __restrict__ xt)
{
    __shared__ float t[32][33];
    const int bh = blockIdx.z;
    const int b = bh >> 4, h = bh & 15;
    const int tt = blockIdx.x * 32;
    const int dd = blockIdx.y * 32;
    const int tx = threadIdx.x, ty = threadIdx.y;
    #pragma unroll
    for (int j = 0; j < 4; j++)
        t[ty + 8*j][tx] = xt[(size_t)(b*T_ + tt + ty + 8*j) * C_ + h*D_ + dd + tx];
    __syncthreads();
    #pragma unroll
    for (int j = 0; j < 4; j++) {
        const int d = dd + ty + 8*j;
        float v = t[tx][ty + 8*j];
        __half hh = __float2half_rn(v);
        const size_t o = ((size_t)bh*D_ + d) * T_ + tt + tx;
        g_vh[o] = hh;
        g_vl[o] = __float2half_rn(v - __half2float(hh));
    }
}

// ----------------------------------------------------------------------------
// GEMM (fp16 2-pass): qk ~= Xh @ (Whi + Wlo) + bias -> split-scatter q/k
// Round-7 skeleton: CTA 128x128, BK=32, 8 warps, 2-stage cp.async,
// ldmatrix frags, padded 40-half rows. 3 smem arrays/stage (Ah, Bh, Bl).
// ----------------------------------------------------------------------------
#define G_ARR (128*40)
#define G_STAGE (3*G_ARR)
#define GEMM_SMEM_BYTES (2*G_STAGE*2)   // 61440

__global__ __launch_bounds__(256, 2) void gemm_qk_kernel(const float* __restrict__ bias)
{
    extern __shared__ __half gsm[];
    const uint32_t smb = (uint32_t)__cvta_generic_to_shared(gsm);

    const int bx = blockIdx.x;
    const int by = blockIdx.y;
    const int tid = threadIdx.x;
    const int warp = tid >> 5;
    const int lane = tid & 31;
    const int lr = lane >> 2;
    const int lc = lane & 3;
    const int wm = warp >> 1;
    const int wn = warp & 1;

    const int aRow = (lane & 15);
    const int aCol = (lane >> 4) * 8;
    const int bRow = ((lane >> 4) << 3) + (lane & 7);
    const int bCol = ((lane >> 3) & 1) * 8;

    float c[2][8][4];
    #pragma unroll
    for (int mt = 0; mt < 2; mt++)
        #pragma unroll
        for (int nt = 0; nt < 8; nt++)
            #pragma unroll
            for (int j = 0; j < 4; j++) c[mt][nt][j] = 0.f;

    auto issue_stage = [&](int stage, int k0) {
        const uint32_t st = smb + (uint32_t)(stage * G_STAGE) * 2;
        #pragma unroll
        for (int i = 0; i < 6; i++) {
            int idx = tid + i * 256;          // 0..1535 16B chunks
            int sec = idx >> 9;               // 0:Ah 1:Bh 2:Bl
            int sub = idx & 511;
            int r   = sub >> 2;               // 0..127
            int c8  = (sub & 3) * 8;
            const __half* src;
            if      (sec == 0) src = g_Xh  + (size_t)(by*128 + r) * K_GEMM + k0 + c8;
            else if (sec == 1) src = g_Whi + (size_t)(bx*128 + r) * K_GEMM + k0 + c8;
            else               src = g_Wlo + (size_t)(bx*128 + r) * K_GEMM + k0 + c8;
            cp_async16(st + (uint32_t)(sec * G_ARR + r * 40 + c8) * 2, src);
        }
        cp_async_commit();
    };

    issue_stage(0, 0);

    const int NIT = K_GEMM / 32;
    for (int it = 0; it < NIT; it++) {
        if (it + 1 < NIT) {
            issue_stage((it + 1) & 1, (it + 1) * 32);
            cp_async_wait<1>();
        } else {
            cp_async_wait<0>();
        }
        __syncthreads();

        const uint32_t Ah = smb + (uint32_t)((it & 1) * G_STAGE) * 2;
        const uint32_t Bh = Ah + G_ARR * 2;
        const uint32_t Bl = Ah + 2 * G_ARR * 2;

        #pragma unroll
        for (int ks = 0; ks < 2; ks++) {
            uint32_t ah[2][4];
            #pragma unroll
            for (int mt = 0; mt < 2; mt++) {
                const uint32_t ao =
                    (uint32_t)(((wm*32 + mt*16 + aRow) * 40) + 16*ks + aCol) * 2;
                ldsm_x4(ah[mt], Ah + ao);
            }
            #pragma unroll
            for (int ntp = 0; ntp < 4; ntp++) {
                const uint32_t bo =
                    (uint32_t)(((wn*64 + ntp*16 + bRow) * 40) + 16*ks + bCol) * 2;
                uint32_t bh4[4], bl4[4];
                ldsm_x4(bh4, Bh + bo);
                ldsm_x4(bl4, Bl + bo);
                #pragma unroll
                for (int half = 0; half < 2; half++)
                    #pragma unroll
                    for (int mt = 0; mt < 2; mt++)
                        mma_fp16(c[mt][2*ntp+half], ah[mt], bh4[2*half], bh4[2*half+1]);
                #pragma unroll
                for (int half = 0; half < 2; half++)
                    #pragma unroll
                    for (int mt = 0; mt < 2; mt++)
                        mma_fp16(c[mt][2*ntp+half], ah[mt], bl4[2*half], bl4[2*half+1]);
            }
        }
        __syncthreads();
    }

    #pragma unroll
    for (int mt = 0; mt < 2; mt++) {
        #pragma unroll
        for (int rr = 0; rr < 2; rr++) {
            const int m = by*128 + wm*32 + mt*16 + rr*8 + lr;
            const int b = m >> 11;
            const int t = m & (T_ - 1);
            #pragma unroll
            for (int nt = 0; nt < 8; nt++) {
                const int n0 = bx*128 + wn*64 + nt*8 + 2*lc;
                const float v0 = c[mt][nt][rr*2 + 0] + bias[n0];
                const float v1 = c[mt][nt][rr*2 + 1] + bias[n0 + 1];
                __half h0 = __float2half_rn(v0);
                __half h1 = __float2half_rn(v1);
                __half l0 = __float2half_rn(v0 - __half2float(h0));
                __half l1 = __float2half_rn(v1 - __half2float(h1));
                if (n0 < C_) {
                    const int hh = n0 >> 6, d = n0 & 63;
                    const size_t o = (((size_t)(b*H_ + hh)) * T_ + t) * D_ + d;
                    *(__half2*)&g_qh[o] = __halves2half2(h0, h1);
                    *(__half2*)&g_ql[o] = __halves2half2(l0, l1);
                } else {
                    const int n2 = n0 - C_;
                    const int hh = n2 >> 6, d = n2 & 63;
                    const size_t o = (((size_t)(b*H_ + hh)) * T_ + t) * D_ + d;
                    *(__half2*)&g_kh[o] = __halves2half2(h0, h1);
                    *(__half2*)&g_kl[o] = __halves2half2(l0, l1);
                }
            }
        }
    }
}

// ----------------------------------------------------------------------------
// Flash attention (round-10 exact): 128 threads / 64 q-rows per CTA,
// fp16 3-pass QK^T and PV, cp.async double-buffered KV, 2 CTAs/SM.
// ----------------------------------------------------------------------------
#define A_STAGE 36864
#define A_PQ    73728
#define ATTN_SMEM_BYTES 92160
#define A_THREADS 128

__global__ __launch_bounds__(A_THREADS) void attn_kernel(float* __restrict__ out)
{
    extern __shared__ char smraw[];
    const uint32_t sm_base = (uint32_t)__cvta_generic_to_shared(smraw);
    __half* Ph  = (__half*)(smraw + A_PQ);
    __half* Pl  = Ph + 64*72;
    const uint32_t PhU = sm_base + A_PQ;
    const uint32_t PlU = PhU + 64*72*2;

    const int bh = blockIdx.y;
    const int b  = bh >> 4;
    const int h  = bh & 15;
    const int tid  = threadIdx.x;
    const int warp = tid >> 5;
    const int lane = tid & 31;
    const int lr = lane >> 2;
    const int lc = lane & 3;
    const int qt = gridDim.x - 1 - blockIdx.x;
    const int t0 = qt * 64;

    const int aRow = (lane & 15);
    const int aCol = (lane >> 4) * 8;
    const int bRow = ((lane >> 4) << 3) + (lane & 7);
    const int bCol = ((lane >> 3) & 1) * 8;

    {
        __half* Qhs = Ph;
        __half* Qls = Pl;
        #pragma unroll
        for (int i = 0; i < 4; i++) {
            int idx = tid + i * A_THREADS;
            int r = idx >> 3, c8 = (idx & 7) * 8;
            *(float4*)&Qhs[r*72 + c8] =
                *(const float4*)(g_qh + ((size_t)bh*T_ + t0 + r)*D_ + c8);
            *(float4*)&Qls[r*72 + c8] =
                *(const float4*)(g_ql + ((size_t)bh*T_ + t0 + r)*D_ + c8);
        }
    }
    __syncthreads();

    uint32_t qfh[4][4], qfl[4][4];
    #pragma unroll
    for (int ks = 0; ks < 4; ks++) {
        const uint32_t qo = (uint32_t)(((warp*16 + aRow) * 72) + 16*ks + aCol) * 2;
        ldsm_x4(qfh[ks], PhU + qo);
        ldsm_x4(qfl[ks], PlU + qo);
    }
    __syncthreads();

    float o[8][4];
    #pragma unroll
    for (int dt = 0; dt < 8; dt++)
        #pragma unroll
        for (int j = 0; j < 4; j++) o[dt][j] = 0.f;

    float m0 = -1e30f, m1 = -1e30f;
    float l0 = 0.f, l1 = 0.f;
    const float C2 = 0.125f * 1.44269504089f;

    const int rg0 = t0 + warp*16 + lr;
    const int rg1 = rg0 + 8;
    const int prow0 = (warp*16 + lr) * 72;
    const int prow1 = prow0 + 8*72;

    auto issue_tile = [&](int stage, int j0) {
        const uint32_t st = sm_base + (uint32_t)stage * A_STAGE;
        #pragma unroll
        for (int i = 0; i < 16; i++) {
            int idx = tid + i * A_THREADS;
            int sec = idx >> 9;
            int sub = idx & 511;
            int r   = sub >> 3;
            int c8  = (sub & 7) * 8;
            const __half* src;
            if      (sec == 0) src = g_kh + ((size_t)bh*T_ + j0 + r)*D_ + c8;
            else if (sec == 1) src = g_kl + ((size_t)bh*T_ + j0 + r)*D_ + c8;
            else if (sec == 2) src = g_vh + ((size_t)bh*D_ + r)*T_ + j0 + c8;
            else               src = g_vl + ((size_t)bh*D_ + r)*T_ + j0 + c8;
            cp_async16(st + (uint32_t)(sec * 9216) + (uint32_t)(r*72 + c8)*2, src);
        }
        cp_async_commit();
    };

    const int ntiles = qt + 1;
    issue_tile(0, 0);

    for (int it = 0; it < ntiles; it++) {
        const int j0 = it * 64;
        if (it + 1 < ntiles) {
            issue_tile((it + 1) & 1, (it + 1) * 64);
            cp_async_wait<1>();
        } else {
            cp_async_wait<0>();
        }
        __syncthreads();

        const uint32_t KhiU = sm_base + (uint32_t)((it & 1) * A_STAGE);
        const uint32_t KloU = KhiU + 9216;
        const uint32_t VhU  = KhiU + 2*9216;
        const uint32_t VlU  = KhiU + 3*9216;

        float s[8][4];
        #pragma unroll
        for (int nt = 0; nt < 8; nt++)
            #pragma unroll
            for (int j = 0; j < 4; j++) s[nt][j] = 0.f;

        #pragma unroll
        for (int ks = 0; ks < 4; ks++) {
            #pragma unroll
            for (int ntp = 0; ntp < 4; ntp++) {
                const uint32_t ko =
                    (uint32_t)(((ntp*16 + bRow) * 72) + 16*ks + bCol) * 2;
                uint32_t kh4[4], kl4[4];
                ldsm_x4(kh4, KhiU + ko);
                ldsm_x4(kl4, KloU + ko);
                #pragma unroll
                for (int half = 0; half < 2; half++) {
                    const int nt = 2*ntp + half;
                    mma_fp16(s[nt], qfh[ks], kh4[2*half], kh4[2*half+1]);
                    mma_fp16(s[nt], qfh[ks], kl4[2*half], kl4[2*half+1]);
                    mma_fp16(s[nt], qfl[ks], kh4[2*half], kh4[2*half+1]);
                }
            }
        }

        if (j0 + 63 > t0) {
            #pragma unroll
            for (int nt = 0; nt < 8; nt++) {
                int cg = j0 + nt*8 + 2*lc;
                if (cg     > rg0) s[nt][0] = -1e30f;
                if (cg + 1 > rg0) s[nt][1] = -1e30f;
                if (cg     > rg1) s[nt][2] = -1e30f;
                if (cg + 1 > rg1) s[nt][3] = -1e30f;
            }
        }

        float t0m = -1e30f, t1m = -1e30f;
        #pragma unroll
        for (int nt = 0; nt < 8; nt++) {
            t0m = fmaxf(t0m, fmaxf(s[nt][0], s[nt][1]));
            t1m = fmaxf(t1m, fmaxf(s[nt][2], s[nt][3]));
        }
        t0m = fmaxf(t0m, __shfl_xor_sync(0xffffffffu, t0m, 1));
        t0m = fmaxf(t0m, __shfl_xor_sync(0xffffffffu, t0m, 2));
        t1m = fmaxf(t1m, __shfl_xor_sync(0xffffffffu, t1m, 1));
        t1m = fmaxf(t1m, __shfl_xor_sync(0xffffffffu, t1m, 2));

        const float mn0 = fmaxf(m0, t0m);
        const float mn1 = fmaxf(m1, t1m);
        const float a0 = ex2f((m0 - mn0) * C2);
        const float a1 = ex2f((m1 - mn1) * C2);
        m0 = mn0; m1 = mn1;
        l0 *= a0; l1 *= a1;
        #pragma unroll
        for (int dt = 0; dt < 8; dt++) {
            o[dt][0] *= a0; o[dt][1] *= a0;
            o[dt][2] *= a1; o[dt][3] *= a1;
        }

        #pragma unroll
        for (int nt = 0; nt < 8; nt++) {
            float p0 = ex2f((s[nt][0] - m0) * C2);
            float p1 = ex2f((s[nt][1] - m0) * C2);
            float p2 = ex2f((s[nt][2] - m1) * C2);
            float p3 = ex2f((s[nt][3] - m1) * C2);
            l0 += p0 + p1;
            l1 += p2 + p3;
            __half h0 = __float2half_rn(p0), h1 = __float2half_rn(p1);
            __half h2 = __float2half_rn(p2), h3 = __float2half_rn(p3);
            *(__half2*)&Ph[prow0 + nt*8 + 2*lc] = __halves2half2(h0, h1);
            *(__half2*)&Ph[prow1 + nt*8 + 2*lc] = __halves2half2(h2, h3);
            *(__half2*)&Pl[prow0 + nt*8 + 2*lc] =
                __halves2half2(__float2half_rn(p0 - __half2float(h0)),
                               __float2half_rn(p1 - __half2float(h1)));
            *(__half2*)&Pl[prow1 + nt*8 + 2*lc] =
                __halves2half2(__float2half_rn(p2 - __half2float(h2)),
                               __float2half_rn(p3 - __half2float(h3)));
        }
        __syncwarp();

        #pragma unroll
        for (int ks = 0; ks < 4; ks++) {
            uint32_t pah[4], pal[4];
            const uint32_t po =
                (uint32_t)(((warp*16 + aRow) * 72) + 16*ks + aCol) * 2;
            ldsm_x4(pah, PhU + po);
            ldsm_x4(pal, PlU + po);
            #pragma unroll
            for (int dtp = 0; dtp < 4; dtp++) {
                const uint32_t vo =
                    (uint32_t)(((dtp*16 + bRow) * 72) + 16*ks + bCol) * 2;
                uint32_t vh4[4], vl4[4];
                ldsm_x4(vh4, VhU + vo);
                ldsm_x4(vl4, VlU + vo);
                #pragma unroll
                for (int half = 0; half < 2; half++) {
                    const int dt = 2*dtp + half;
                    mma_fp16(o[dt], pah, vh4[2*half], vh4[2*half+1]);
                    mma_fp16(o[dt], pah, vl4[2*half], vl4[2*half+1]);
                    mma_fp16(o[dt], pal, vh4[2*half], vh4[2*half+1]);
                }
            }
        }
        __syncthreads();
    }

    l0 += __shfl_xor_sync(0xffffffffu, l0, 1);
    l0 += __shfl_xor_sync(0xffffffffu, l0, 2);
    l1 += __shfl_xor_sync(0xffffffffu, l1, 1);
    l1 += __shfl_xor_sync(0xffffffffu, l1, 2);
    const float inv0 = 1.f / l0;
    const float inv1 = 1.f / l1;

    float* out0 = out + ((size_t)(b*T_ + rg0))*C_ + h*D_;
    float* out1 = out + ((size_t)(b*T_ + rg1))*C_ + h*D_;
    #pragma unroll
    for (int dt = 0; dt < 8; dt++) {
        *(float2*)(out0 + dt*8 + 2*lc) = make_float2(o[dt][0]*inv0, o[dt][1]*inv0);
        *(float2*)(out1 + dt*8 + 2*lc) = make_float2(o[dt][2]*inv1, o[dt][3]*inv1);
    }
}

// ----------------------------------------------------------------------------
extern "C" void kernel_launch(void* const* d_in, const int* in_sizes, int n_in,
                              void* d_out, int out_size)
{
    const float* x_norm = (const float*)d_in[0];
    const float* xt_cur = (const float*)d_in[1];
    const float* W_attn = (const float*)d_in[2];
    const float* b_attn = (const float*)d_in[3];
    float* out = (float*)d_out;

    cudaFuncSetAttribute(gemm_qk_kernel,
                         cudaFuncAttributeMaxDynamicSharedMemorySize, GEMM_SMEM_BYTES);
    cudaFuncSetAttribute(attn_kernel,
                         cudaFuncAttributeMaxDynamicSharedMemorySize, ATTN_SMEM_BYTES);

    prep_x_kernel<<<(M_GEMM*K_GEMM/2)/256, 256>>>(x_norm);
    prep_w_kernel<<<dim3(N_GEMM/32, K_GEMM/32), dim3(32, 8)>>>(W_attn);
    prep_v_kernel<<<dim3(T_/32, D_/32, BH_), dim3(32, 8)>>>(xt_cur);

    dim3 g1(N_GEMM/128, M_GEMM/128);   // (16, 32)
    gemm_qk_kernel<<<g1, 256, GEMM_SMEM_BYTES>>>(b_attn);

    dim3 g2(T_/64, B_*H_);             // (32, 32)
    attn_kernel<<<g2, A_THREADS, ATTN_SMEM_BYTES>>>(out);
}

// round 13
// speedup vs baseline: 1.2911x; 1.1261x over previous
#include <cuda_runtime.h>
#include <cuda_fp16.h>
#include <cstdint>

// ============================================================================
// FactoredCausalSelfAttention  (B=2, T=2048, C=1024, H=16, D=64)
// Round 13: attn cut to 2-pass both matmuls:
//   QK: qh*(kh+kl)   (q-lo dropped entirely)
//   PV: ph*(vh+vl)   (P-lo dropped; l accumulated from rounded Ph for
//                     numerator/denominator consistency)
// gemm = round-12 exact (2-pass). Predicted rel_err ~3.5e-4.
// ============================================================================

#define B_   2
#define T_   2048
#define C_   1024
#define H_   16
#define D_   64
#define BH_  (B_*H_)
#define M_GEMM (B_*T_)      // 4096
#define N_GEMM (2*C_)       // 2048
#define K_GEMM (C_)         // 1024

// ---- device scratch ----
__device__ __align__(16) __half g_Xh [(size_t)M_GEMM*K_GEMM];
__device__ __align__(16) __half g_Whi[(size_t)N_GEMM*K_GEMM];  // [n][k]
__device__ __align__(16) __half g_Wlo[(size_t)N_GEMM*K_GEMM];  // [n][k]
__device__ __align__(16) __half g_qh [(size_t)BH_*T_*D_];      // [bh][t][d]
__device__ __align__(16) __half g_kh [(size_t)BH_*T_*D_];
__device__ __align__(16) __half g_kl [(size_t)BH_*T_*D_];
__device__ __align__(16) __half g_vh [(size_t)BH_*D_*T_];      // [bh][d][t]
__device__ __align__(16) __half g_vl [(size_t)BH_*D_*T_];

// ---------------------------------------------------------------- helpers ---
__device__ __forceinline__ void mma_fp16(float c[4], const uint32_t a[4],
                                         uint32_t b0, uint32_t b1)
{
    asm volatile(
        "mma.sync.aligned.m16n8k16.row.col.f32.f16.f16.f32 "
        "{%0,%1,%2,%3}, {%4,%5,%6,%7}, {%8,%9}, {%0,%1,%2,%3};\n"
        : "+f"(c[0]), "+f"(c[1]), "+f"(c[2]), "+f"(c[3])
        : "r"(a[0]), "r"(a[1]), "r"(a[2]), "r"(a[3]), "r"(b0), "r"(b1));
}

__device__ __forceinline__ void ldsm_x4(uint32_t r[4], uint32_t addr)
{
    asm volatile("ldmatrix.sync.aligned.m8n8.x4.shared.b16 {%0,%1,%2,%3}, [%4];"
                 : "=r"(r[0]), "=r"(r[1]), "=r"(r[2]), "=r"(r[3]) : "r"(addr));
}

__device__ __forceinline__ float ex2f(float x) {
    float y;
    asm("ex2.approx.f32 %0, %1;" : "=f"(y) : "f"(x));
    return y;
}

__device__ __forceinline__ void cp_async16(uint32_t smem_addr, const void* gptr) {
    asm volatile("cp.async.ca.shared.global [%0], [%1], 16;\n"
                 :: "r"(smem_addr), "l"(gptr));
}
__device__ __forceinline__ void cp_async_commit() {
    asm volatile("cp.async.commit_group;\n");
}
template<int N>
__device__ __forceinline__ void cp_async_wait() {
    asm volatile("cp.async.wait_group %0;\n" :: "n"(N));
}

// ----------------------------------------------------------------------------
// prep kernels
// ----------------------------------------------------------------------------
__global__ __launch_bounds__(256) void prep_x_kernel(const float* __restrict__ X)
{
    int i = blockIdx.x * 256 + threadIdx.x;
    float2 v = ((const float2*)X)[i];
    ((__half2*)g_Xh)[i] = __halves2half2(__float2half_rn(v.x), __float2half_rn(v.y));
}

__global__ __launch_bounds__(256) void prep_w_kernel(const float* __restrict__ W)
{
    __shared__ float t[32][33];
    const int bn = blockIdx.x, bk = blockIdx.y;
    const int tx = threadIdx.x, ty = threadIdx.y;
    #pragma unroll
    for (int j = 0; j < 4; j++)
        t[ty + 8*j][tx] = W[(size_t)(bk*32 + ty + 8*j) * N_GEMM + bn*32 + tx];
    __syncthreads();
    #pragma unroll
    for (int j = 0; j < 4; j++) {
        const int n = bn*32 + ty + 8*j;
        const int k = bk*32 + tx;
        float v = t[tx][ty + 8*j];
        __half h = __float2half_rn(v);
        g_Whi[(size_t)n * K_GEMM + k] = h;
        g_Wlo[(size_t)n * K_GEMM + k] = __float2half_rn(v - __half2float(h));
    }
}

__global__ __launch_bounds__(256) void prep_v_kernel(const float* __restrict__ xt)
{
    __shared__ float t[32][33];
    const int bh = blockIdx.z;
    const int b = bh >> 4, h = bh & 15;
    const int tt = blockIdx.x * 32;
    const int dd = blockIdx.y * 32;
    const int tx = threadIdx.x, ty = threadIdx.y;
    #pragma unroll
    for (int j = 0; j < 4; j++)
        t[ty + 8*j][tx] = xt[(size_t)(b*T_ + tt + ty + 8*j) * C_ + h*D_ + dd + tx];
    __syncthreads();
    #pragma unroll
    for (int j = 0; j < 4; j++) {
        const int d = dd + ty + 8*j;
        float v = t[tx][ty + 8*j];
        __half hh = __float2half_rn(v);
        const size_t o = ((size_t)bh*D_ + d) * T_ + tt + tx;
        g_vh[o] = hh;
        g_vl[o] = __float2half_rn(v - __half2float(hh));
    }
}

// ----------------------------------------------------------------------------
// GEMM (fp16 2-pass, round-12 exact): qk ~= Xh @ (Whi + Wlo) + bias
// q scattered hi-only; k scattered hi/lo.
// ----------------------------------------------------------------------------
#define G_ARR (128*40)
#define G_STAGE (3*G_ARR)
#define GEMM_SMEM_BYTES (2*G_STAGE*2)   // 61440

__global__ __launch_bounds__(256, 2) void gemm_qk_kernel(const float* __restrict__ bias)
{
    extern __shared__ __half gsm[];
    const uint32_t smb = (uint32_t)__cvta_generic_to_shared(gsm);

    const int bx = blockIdx.x;
    const int by = blockIdx.y;
    const int tid = threadIdx.x;
    const int warp = tid >> 5;
    const int lane = tid & 31;
    const int lr = lane >> 2;
    const int lc = lane & 3;
    const int wm = warp >> 1;
    const int wn = warp & 1;

    const int aRow = (lane & 15);
    const int aCol = (lane >> 4) * 8;
    const int bRow = ((lane >> 4) << 3) + (lane & 7);
    const int bCol = ((lane >> 3) & 1) * 8;

    float c[2][8][4];
    #pragma unroll
    for (int mt = 0; mt < 2; mt++)
        #pragma unroll
        for (int nt = 0; nt < 8; nt++)
            #pragma unroll
            for (int j = 0; j < 4; j++) c[mt][nt][j] = 0.f;

    auto issue_stage = [&](int stage, int k0) {
        const uint32_t st = smb + (uint32_t)(stage * G_STAGE) * 2;
        #pragma unroll
        for (int i = 0; i < 6; i++) {
            int idx = tid + i * 256;
            int sec = idx >> 9;               // 0:Ah 1:Bh 2:Bl
            int sub = idx & 511;
            int r   = sub >> 2;
            int c8  = (sub & 3) * 8;
            const __half* src;
            if      (sec == 0) src = g_Xh  + (size_t)(by*128 + r) * K_GEMM + k0 + c8;
            else if (sec == 1) src = g_Whi + (size_t)(bx*128 + r) * K_GEMM + k0 + c8;
            else               src = g_Wlo + (size_t)(bx*128 + r) * K_GEMM + k0 + c8;
            cp_async16(st + (uint32_t)(sec * G_ARR + r * 40 + c8) * 2, src);
        }
        cp_async_commit();
    };

    issue_stage(0, 0);

    const int NIT = K_GEMM / 32;
    for (int it = 0; it < NIT; it++) {
        if (it + 1 < NIT) {
            issue_stage((it + 1) & 1, (it + 1) * 32);
            cp_async_wait<1>();
        } else {
            cp_async_wait<0>();
        }
        __syncthreads();

        const uint32_t Ah = smb + (uint32_t)((it & 1) * G_STAGE) * 2;
        const uint32_t Bh = Ah + G_ARR * 2;
        const uint32_t Bl = Ah + 2 * G_ARR * 2;

        #pragma unroll
        for (int ks = 0; ks < 2; ks++) {
            uint32_t ah[2][4];
            #pragma unroll
            for (int mt = 0; mt < 2; mt++) {
                const uint32_t ao =
                    (uint32_t)(((wm*32 + mt*16 + aRow) * 40) + 16*ks + aCol) * 2;
                ldsm_x4(ah[mt], Ah + ao);
            }
            #pragma unroll
            for (int ntp = 0; ntp < 4; ntp++) {
                const uint32_t bo =
                    (uint32_t)(((wn*64 + ntp*16 + bRow) * 40) + 16*ks + bCol) * 2;
                uint32_t bh4[4], bl4[4];
                ldsm_x4(bh4, Bh + bo);
                ldsm_x4(bl4, Bl + bo);
                #pragma unroll
                for (int half = 0; half < 2; half++)
                    #pragma unroll
                    for (int mt = 0; mt < 2; mt++)
                        mma_fp16(c[mt][2*ntp+half], ah[mt], bh4[2*half], bh4[2*half+1]);
                #pragma unroll
                for (int half = 0; half < 2; half++)
                    #pragma unroll
                    for (int mt = 0; mt < 2; mt++)
                        mma_fp16(c[mt][2*ntp+half], ah[mt], bl4[2*half], bl4[2*half+1]);
            }
        }
        __syncthreads();
    }

    #pragma unroll
    for (int mt = 0; mt < 2; mt++) {
        #pragma unroll
        for (int rr = 0; rr < 2; rr++) {
            const int m = by*128 + wm*32 + mt*16 + rr*8 + lr;
            const int b = m >> 11;
            const int t = m & (T_ - 1);
            #pragma unroll
            for (int nt = 0; nt < 8; nt++) {
                const int n0 = bx*128 + wn*64 + nt*8 + 2*lc;
                const float v0 = c[mt][nt][rr*2 + 0] + bias[n0];
                const float v1 = c[mt][nt][rr*2 + 1] + bias[n0 + 1];
                __half h0 = __float2half_rn(v0);
                __half h1 = __float2half_rn(v1);
                if (n0 < C_) {
                    const int hh = n0 >> 6, d = n0 & 63;
                    const size_t o = (((size_t)(b*H_ + hh)) * T_ + t) * D_ + d;
                    *(__half2*)&g_qh[o] = __halves2half2(h0, h1);
                } else {
                    const int n2 = n0 - C_;
                    const int hh = n2 >> 6, d = n2 & 63;
                    const size_t o = (((size_t)(b*H_ + hh)) * T_ + t) * D_ + d;
                    *(__half2*)&g_kh[o] = __halves2half2(h0, h1);
                    *(__half2*)&g_kl[o] =
                        __halves2half2(__float2half_rn(v0 - __half2float(h0)),
                                       __float2half_rn(v1 - __half2float(h1)));
                }
            }
        }
    }
}

// ----------------------------------------------------------------------------
// Flash attention: 128 threads / 64 q-rows per CTA, 2-pass QK and PV.
// smem: stage s @ s*36864: Khi[64][72] Klo Vh Vl (half, 9216B each)
//       Ph[64][72] @ 73728 (Q staging aliases it)   -> total 82944B
// ----------------------------------------------------------------------------
#define A_STAGE 36864
#define A_PQ    73728
#define ATTN_SMEM_BYTES 82944
#define A_THREADS 128

__global__ __launch_bounds__(A_THREADS) void attn_kernel(float* __restrict__ out)
{
    extern __shared__ char smraw[];
    const uint32_t sm_base = (uint32_t)__cvta_generic_to_shared(smraw);
    __half* Ph  = (__half*)(smraw + A_PQ);
    const uint32_t PhU = sm_base + A_PQ;

    const int bh = blockIdx.y;
    const int b  = bh >> 4;
    const int h  = bh & 15;
    const int tid  = threadIdx.x;
    const int warp = tid >> 5;
    const int lane = tid & 31;
    const int lr = lane >> 2;
    const int lc = lane & 3;
    const int qt = gridDim.x - 1 - blockIdx.x;
    const int t0 = qt * 64;

    const int aRow = (lane & 15);
    const int aCol = (lane >> 4) * 8;
    const int bRow = ((lane >> 4) << 3) + (lane & 7);
    const int bCol = ((lane >> 3) & 1) * 8;

    // ---- stage Qh into Ph region ----
    #pragma unroll
    for (int i = 0; i < 4; i++) {
        int idx = tid + i * A_THREADS;      // 0..511 float4s
        if (idx < 512) {
            int r = idx >> 3, c8 = (idx & 7) * 8;
            *(float4*)&Ph[r*72 + c8] =
                *(const float4*)(g_qh + ((size_t)bh*T_ + t0 + r)*D_ + c8);
        }
    }
    __syncthreads();

    uint32_t qfh[4][4];
    #pragma unroll
    for (int ks = 0; ks < 4; ks++) {
        const uint32_t qo = (uint32_t)(((warp*16 + aRow) * 72) + 16*ks + aCol) * 2;
        ldsm_x4(qfh[ks], PhU + qo);
    }
    __syncthreads();

    float o[8][4];
    #pragma unroll
    for (int dt = 0; dt < 8; dt++)
        #pragma unroll
        for (int j = 0; j < 4; j++) o[dt][j] = 0.f;

    float m0 = -1e30f, m1 = -1e30f;
    float l0 = 0.f, l1 = 0.f;
    const float C2 = 0.125f * 1.44269504089f;

    const int rg0 = t0 + warp*16 + lr;
    const int rg1 = rg0 + 8;
    const int prow0 = (warp*16 + lr) * 72;
    const int prow1 = prow0 + 8*72;

    auto issue_tile = [&](int stage, int j0) {
        const uint32_t st = sm_base + (uint32_t)stage * A_STAGE;
        #pragma unroll
        for (int i = 0; i < 16; i++) {
            int idx = tid + i * A_THREADS;
            int sec = idx >> 9;
            int sub = idx & 511;
            int r   = sub >> 3;
            int c8  = (sub & 7) * 8;
            const __half* src;
            if      (sec == 0) src = g_kh + ((size_t)bh*T_ + j0 + r)*D_ + c8;
            else if (sec == 1) src = g_kl + ((size_t)bh*T_ + j0 + r)*D_ + c8;
            else if (sec == 2) src = g_vh + ((size_t)bh*D_ + r)*T_ + j0 + c8;
            else               src = g_vl + ((size_t)bh*D_ + r)*T_ + j0 + c8;
            cp_async16(st + (uint32_t)(sec * 9216) + (uint32_t)(r*72 + c8)*2, src);
        }
        cp_async_commit();
    };

    const int ntiles = qt + 1;
    issue_tile(0, 0);

    for (int it = 0; it < ntiles; it++) {
        const int j0 = it * 64;
        if (it + 1 < ntiles) {
            issue_tile((it + 1) & 1, (it + 1) * 64);
            cp_async_wait<1>();
        } else {
            cp_async_wait<0>();
        }
        __syncthreads();

        const uint32_t KhiU = sm_base + (uint32_t)((it & 1) * A_STAGE);
        const uint32_t KloU = KhiU + 9216;
        const uint32_t VhU  = KhiU + 2*9216;
        const uint32_t VlU  = KhiU + 3*9216;

        // ---- S = Qh (Kh + Kl)^T  (2-pass) ----
        float s[8][4];
        #pragma unroll
        for (int nt = 0; nt < 8; nt++)
            #pragma unroll
            for (int j = 0; j < 4; j++) s[nt][j] = 0.f;

        #pragma unroll
        for (int ks = 0; ks < 4; ks++) {
            #pragma unroll
            for (int ntp = 0; ntp < 4; ntp++) {
                const uint32_t ko =
                    (uint32_t)(((ntp*16 + bRow) * 72) + 16*ks + bCol) * 2;
                uint32_t kh4[4], kl4[4];
                ldsm_x4(kh4, KhiU + ko);
                ldsm_x4(kl4, KloU + ko);
                #pragma unroll
                for (int half = 0; half < 2; half++) {
                    const int nt = 2*ntp + half;
                    mma_fp16(s[nt], qfh[ks], kh4[2*half], kh4[2*half+1]);
                    mma_fp16(s[nt], qfh[ks], kl4[2*half], kl4[2*half+1]);
                }
            }
        }

        // ---- causal mask ----
        if (j0 + 63 > t0) {
            #pragma unroll
            for (int nt = 0; nt < 8; nt++) {
                int cg = j0 + nt*8 + 2*lc;
                if (cg     > rg0) s[nt][0] = -1e30f;
                if (cg + 1 > rg0) s[nt][1] = -1e30f;
                if (cg     > rg1) s[nt][2] = -1e30f;
                if (cg + 1 > rg1) s[nt][3] = -1e30f;
            }
        }

        // ---- online softmax ----
        float t0m = -1e30f, t1m = -1e30f;
        #pragma unroll
        for (int nt = 0; nt < 8; nt++) {
            t0m = fmaxf(t0m, fmaxf(s[nt][0], s[nt][1]));
            t1m = fmaxf(t1m, fmaxf(s[nt][2], s[nt][3]));
        }
        t0m = fmaxf(t0m, __shfl_xor_sync(0xffffffffu, t0m, 1));
        t0m = fmaxf(t0m, __shfl_xor_sync(0xffffffffu, t0m, 2));
        t1m = fmaxf(t1m, __shfl_xor_sync(0xffffffffu, t1m, 1));
        t1m = fmaxf(t1m, __shfl_xor_sync(0xffffffffu, t1m, 2));

        const float mn0 = fmaxf(m0, t0m);
        const float mn1 = fmaxf(m1, t1m);
        const float a0 = ex2f((m0 - mn0) * C2);
        const float a1 = ex2f((m1 - mn1) * C2);
        m0 = mn0; m1 = mn1;
        l0 *= a0; l1 *= a1;
        #pragma unroll
        for (int dt = 0; dt < 8; dt++) {
            o[dt][0] *= a0; o[dt][1] *= a0;
            o[dt][2] *= a1; o[dt][3] *= a1;
        }

        // ---- p -> fp16 (rounded); l accumulated from ROUNDED values ----
        #pragma unroll
        for (int nt = 0; nt < 8; nt++) {
            float p0 = ex2f((s[nt][0] - m0) * C2);
            float p1 = ex2f((s[nt][1] - m0) * C2);
            float p2 = ex2f((s[nt][2] - m1) * C2);
            float p3 = ex2f((s[nt][3] - m1) * C2);
            __half h0 = __float2half_rn(p0), h1 = __float2half_rn(p1);
            __half h2 = __float2half_rn(p2), h3 = __float2half_rn(p3);
            l0 += __half2float(h0) + __half2float(h1);
            l1 += __half2float(h2) + __half2float(h3);
            *(__half2*)&Ph[prow0 + nt*8 + 2*lc] = __halves2half2(h0, h1);
            *(__half2*)&Ph[prow1 + nt*8 + 2*lc] = __halves2half2(h2, h3);
        }
        __syncwarp();   // P rows are per-warp private

        // ---- O += Ph (Vh + Vl)  (2-pass) ----
        #pragma unroll
        for (int ks = 0; ks < 4; ks++) {
            uint32_t pah[4];
            const uint32_t po =
                (uint32_t)(((warp*16 + aRow) * 72) + 16*ks + aCol) * 2;
            ldsm_x4(pah, PhU + po);
            #pragma unroll
            for (int dtp = 0; dtp < 4; dtp++) {
                const uint32_t vo =
                    (uint32_t)(((dtp*16 + bRow) * 72) + 16*ks + bCol) * 2;
                uint32_t vh4[4], vl4[4];
                ldsm_x4(vh4, VhU + vo);
                ldsm_x4(vl4, VlU + vo);
                #pragma unroll
                for (int half = 0; half < 2; half++) {
                    const int dt = 2*dtp + half;
                    mma_fp16(o[dt], pah, vh4[2*half], vh4[2*half+1]);
                    mma_fp16(o[dt], pah, vl4[2*half], vl4[2*half+1]);
                }
            }
        }
        __syncthreads();
    }

    // ---- finalize ----
    l0 += __shfl_xor_sync(0xffffffffu, l0, 1);
    l0 += __shfl_xor_sync(0xffffffffu, l0, 2);
    l1 += __shfl_xor_sync(0xffffffffu, l1, 1);
    l1 += __shfl_xor_sync(0xffffffffu, l1, 2);
    const float inv0 = 1.f / l0;
    const float inv1 = 1.f / l1;

    float* out0 = out + ((size_t)(b*T_ + rg0))*C_ + h*D_;
    float* out1 = out + ((size_t)(b*T_ + rg1))*C_ + h*D_;
    #pragma unroll
    for (int dt = 0; dt < 8; dt++) {
        *(float2*)(out0 + dt*8 + 2*lc) = make_float2(o[dt][0]*inv0, o[dt][1]*inv0);
        *(float2*)(out1 + dt*8 + 2*lc) = make_float2(o[dt][2]*inv1, o[dt][3]*inv1);
    }
}

// ----------------------------------------------------------------------------
extern "C" void kernel_launch(void* const* d_in, const int* in_sizes, int n_in,
                              void* d_out, int out_size)
{
    const float* x_norm = (const float*)d_in[0];
    const float* xt_cur = (const float*)d_in[1];
    const float* W_attn = (const float*)d_in[2];
    const float* b_attn = (const float*)d_in[3];
    float* out = (float*)d_out;

    cudaFuncSetAttribute(gemm_qk_kernel,
                         cudaFuncAttributeMaxDynamicSharedMemorySize, GEMM_SMEM_BYTES);
    cudaFuncSetAttribute(attn_kernel,
                         cudaFuncAttributeMaxDynamicSharedMemorySize, ATTN_SMEM_BYTES);

    prep_x_kernel<<<(M_GEMM*K_GEMM/2)/256, 256>>>(x_norm);
    prep_w_kernel<<<dim3(N_GEMM/32, K_GEMM/32), dim3(32, 8)>>>(W_attn);
    prep_v_kernel<<<dim3(T_/32, D_/32, BH_), dim3(32, 8)>>>(xt_cur);

    dim3 g1(N_GEMM/128, M_GEMM/128);   // (16, 32)
    gemm_qk_kernel<<<g1, 256, GEMM_SMEM_BYTES>>>(b_attn);

    dim3 g2(T_/64, B_*H_);             // (32, 32)
    attn_kernel<<<g2, A_THREADS, ATTN_SMEM_BYTES>>>(out);
}

// round 15
// speedup vs baseline: 1.6740x; 1.2966x over previous
#include <cuda_runtime.h>
#include <cuda_fp16.h>
#include <cstdint>

// ============================================================================
// FactoredCausalSelfAttention  (B=2, T=2048, C=1024, H=16, D=64)
// Round 15: round-14 with the KV tile loader coverage bug fixed
//           (1024 16B chunks per stage, full 64-half rows).
//           attn 1-pass QK/PV; K,V fp16-hi only; gemm 2-pass (round-12).
// ============================================================================

#define B_   2
#define T_   2048
#define C_   1024
#define H_   16
#define D_   64
#define BH_  (B_*H_)
#define M_GEMM (B_*T_)      // 4096
#define N_GEMM (2*C_)       // 2048
#define K_GEMM (C_)         // 1024

// ---- device scratch ----
__device__ __align__(16) __half g_Xh [(size_t)M_GEMM*K_GEMM];
__device__ __align__(16) __half g_Whi[(size_t)N_GEMM*K_GEMM];  // [n][k]
__device__ __align__(16) __half g_Wlo[(size_t)N_GEMM*K_GEMM];  // [n][k]
__device__ __align__(16) __half g_qh [(size_t)BH_*T_*D_];      // [bh][t][d]
__device__ __align__(16) __half g_kh [(size_t)BH_*T_*D_];
__device__ __align__(16) __half g_vh [(size_t)BH_*D_*T_];      // [bh][d][t]

// ---------------------------------------------------------------- helpers ---
__device__ __forceinline__ void mma_fp16(float c[4], const uint32_t a[4],
                                         uint32_t b0, uint32_t b1)
{
    asm volatile(
        "mma.sync.aligned.m16n8k16.row.col.f32.f16.f16.f32 "
        "{%0,%1,%2,%3}, {%4,%5,%6,%7}, {%8,%9}, {%0,%1,%2,%3};\n"
        : "+f"(c[0]), "+f"(c[1]), "+f"(c[2]), "+f"(c[3])
        : "r"(a[0]), "r"(a[1]), "r"(a[2]), "r"(a[3]), "r"(b0), "r"(b1));
}

__device__ __forceinline__ void ldsm_x4(uint32_t r[4], uint32_t addr)
{
    asm volatile("ldmatrix.sync.aligned.m8n8.x4.shared.b16 {%0,%1,%2,%3}, [%4];"
                 : "=r"(r[0]), "=r"(r[1]), "=r"(r[2]), "=r"(r[3]) : "r"(addr));
}

__device__ __forceinline__ float ex2f(float x) {
    float y;
    asm("ex2.approx.f32 %0, %1;" : "=f"(y) : "f"(x));
    return y;
}

__device__ __forceinline__ void cp_async16(uint32_t smem_addr, const void* gptr) {
    asm volatile("cp.async.ca.shared.global [%0], [%1], 16;\n"
                 :: "r"(smem_addr), "l"(gptr));
}
__device__ __forceinline__ void cp_async_commit() {
    asm volatile("cp.async.commit_group;\n");
}
template<int N>
__device__ __forceinline__ void cp_async_wait() {
    asm volatile("cp.async.wait_group %0;\n" :: "n"(N));
}

// ----------------------------------------------------------------------------
// prep kernels
// ----------------------------------------------------------------------------
__global__ __launch_bounds__(256) void prep_x_kernel(const float* __restrict__ X)
{
    int i = blockIdx.x * 256 + threadIdx.x;
    float2 v = ((const float2*)X)[i];
    ((__half2*)g_Xh)[i] = __halves2half2(__float2half_rn(v.x), __float2half_rn(v.y));
}

__global__ __launch_bounds__(256) void prep_w_kernel(const float* __restrict__ W)
{
    __shared__ float t[32][33];
    const int bn = blockIdx.x, bk = blockIdx.y;
    const int tx = threadIdx.x, ty = threadIdx.y;
    #pragma unroll
    for (int j = 0; j < 4; j++)
        t[ty + 8*j][tx] = W[(size_t)(bk*32 + ty + 8*j) * N_GEMM + bn*32 + tx];
    __syncthreads();
    #pragma unroll
    for (int j = 0; j < 4; j++) {
        const int n = bn*32 + ty + 8*j;
        const int k = bk*32 + tx;
        float v = t[tx][ty + 8*j];
        __half h = __float2half_rn(v);
        g_Whi[(size_t)n * K_GEMM + k] = h;
        g_Wlo[(size_t)n * K_GEMM + k] = __float2half_rn(v - __half2float(h));
    }
}

__global__ __launch_bounds__(256) void prep_v_kernel(const float* __restrict__ xt)
{
    __shared__ float t[32][33];
    const int bh = blockIdx.z;
    const int b = bh >> 4, h = bh & 15;
    const int tt = blockIdx.x * 32;
    const int dd = blockIdx.y * 32;
    const int tx = threadIdx.x, ty = threadIdx.y;
    #pragma unroll
    for (int j = 0; j < 4; j++)
        t[ty + 8*j][tx] = xt[(size_t)(b*T_ + tt + ty + 8*j) * C_ + h*D_ + dd + tx];
    __syncthreads();
    #pragma unroll
    for (int j = 0; j < 4; j++) {
        const int d = dd + ty + 8*j;
        g_vh[((size_t)bh*D_ + d) * T_ + tt + tx] = __float2half_rn(t[tx][ty + 8*j]);
    }
}

// ----------------------------------------------------------------------------
// GEMM (fp16 2-pass, round-12 exact): qk ~= Xh @ (Whi + Wlo) + bias
// epilogue: q and k both stored fp16-hi only (head-transposed).
// ----------------------------------------------------------------------------
#define G_ARR (128*40)
#define G_STAGE (3*G_ARR)
#define GEMM_SMEM_BYTES (2*G_STAGE*2)   // 61440

__global__ __launch_bounds__(256, 2) void gemm_qk_kernel(const float* __restrict__ bias)
{
    extern __shared__ __half gsm[];
    const uint32_t smb = (uint32_t)__cvta_generic_to_shared(gsm);

    const int bx = blockIdx.x;
    const int by = blockIdx.y;
    const int tid = threadIdx.x;
    const int warp = tid >> 5;
    const int lane = tid & 31;
    const int lr = lane >> 2;
    const int lc = lane & 3;
    const int wm = warp >> 1;
    const int wn = warp & 1;

    const int aRow = (lane & 15);
    const int aCol = (lane >> 4) * 8;
    const int bRow = ((lane >> 4) << 3) + (lane & 7);
    const int bCol = ((lane >> 3) & 1) * 8;

    float c[2][8][4];
    #pragma unroll
    for (int mt = 0; mt < 2; mt++)
        #pragma unroll
        for (int nt = 0; nt < 8; nt++)
            #pragma unroll
            for (int j = 0; j < 4; j++) c[mt][nt][j] = 0.f;

    auto issue_stage = [&](int stage, int k0) {
        const uint32_t st = smb + (uint32_t)(stage * G_STAGE) * 2;
        #pragma unroll
        for (int i = 0; i < 6; i++) {
            int idx = tid + i * 256;
            int sec = idx >> 9;               // 0:Ah 1:Bh 2:Bl
            int sub = idx & 511;
            int r   = sub >> 2;
            int c8  = (sub & 3) * 8;
            const __half* src;
            if      (sec == 0) src = g_Xh  + (size_t)(by*128 + r) * K_GEMM + k0 + c8;
            else if (sec == 1) src = g_Whi + (size_t)(bx*128 + r) * K_GEMM + k0 + c8;
            else               src = g_Wlo + (size_t)(bx*128 + r) * K_GEMM + k0 + c8;
            cp_async16(st + (uint32_t)(sec * G_ARR + r * 40 + c8) * 2, src);
        }
        cp_async_commit();
    };

    issue_stage(0, 0);

    const int NIT = K_GEMM / 32;
    for (int it = 0; it < NIT; it++) {
        if (it + 1 < NIT) {
            issue_stage((it + 1) & 1, (it + 1) * 32);
            cp_async_wait<1>();
        } else {
            cp_async_wait<0>();
        }
        __syncthreads();

        const uint32_t Ah = smb + (uint32_t)((it & 1) * G_STAGE) * 2;
        const uint32_t Bh = Ah + G_ARR * 2;
        const uint32_t Bl = Ah + 2 * G_ARR * 2;

        #pragma unroll
        for (int ks = 0; ks < 2; ks++) {
            uint32_t ah[2][4];
            #pragma unroll
            for (int mt = 0; mt < 2; mt++) {
                const uint32_t ao =
                    (uint32_t)(((wm*32 + mt*16 + aRow) * 40) + 16*ks + aCol) * 2;
                ldsm_x4(ah[mt], Ah + ao);
            }
            #pragma unroll
            for (int ntp = 0; ntp < 4; ntp++) {
                const uint32_t bo =
                    (uint32_t)(((wn*64 + ntp*16 + bRow) * 40) + 16*ks + bCol) * 2;
                uint32_t bh4[4], bl4[4];
                ldsm_x4(bh4, Bh + bo);
                ldsm_x4(bl4, Bl + bo);
                #pragma unroll
                for (int half = 0; half < 2; half++)
                    #pragma unroll
                    for (int mt = 0; mt < 2; mt++)
                        mma_fp16(c[mt][2*ntp+half], ah[mt], bh4[2*half], bh4[2*half+1]);
                #pragma unroll
                for (int half = 0; half < 2; half++)
                    #pragma unroll
                    for (int mt = 0; mt < 2; mt++)
                        mma_fp16(c[mt][2*ntp+half], ah[mt], bl4[2*half], bl4[2*half+1]);
            }
        }
        __syncthreads();
    }

    #pragma unroll
    for (int mt = 0; mt < 2; mt++) {
        #pragma unroll
        for (int rr = 0; rr < 2; rr++) {
            const int m = by*128 + wm*32 + mt*16 + rr*8 + lr;
            const int b = m >> 11;
            const int t = m & (T_ - 1);
            #pragma unroll
            for (int nt = 0; nt < 8; nt++) {
                const int n0 = bx*128 + wn*64 + nt*8 + 2*lc;
                const float v0 = c[mt][nt][rr*2 + 0] + bias[n0];
                const float v1 = c[mt][nt][rr*2 + 1] + bias[n0 + 1];
                const __half2 hv =
                    __halves2half2(__float2half_rn(v0), __float2half_rn(v1));
                if (n0 < C_) {
                    const int hh = n0 >> 6, d = n0 & 63;
                    *(__half2*)&g_qh[(((size_t)(b*H_ + hh)) * T_ + t) * D_ + d] = hv;
                } else {
                    const int n2 = n0 - C_;
                    const int hh = n2 >> 6, d = n2 & 63;
                    *(__half2*)&g_kh[(((size_t)(b*H_ + hh)) * T_ + t) * D_ + d] = hv;
                }
            }
        }
    }
}

// ----------------------------------------------------------------------------
// Flash attention: 128 threads / 64 q-rows per CTA, 1-pass QK and PV.
// smem: stage s @ s*18432: Kh[64][72] @ 0, Vh[64][72] @ 9216 (half)
//       Ph[64][72] @ 36864 (Q staging aliases it)  -> total 46080B
// ----------------------------------------------------------------------------
#define A_STAGE 18432
#define A_PQ    36864
#define ATTN_SMEM_BYTES 46080
#define A_THREADS 128

__global__ __launch_bounds__(A_THREADS) void attn_kernel(float* __restrict__ out)
{
    extern __shared__ char smraw[];
    const uint32_t sm_base = (uint32_t)__cvta_generic_to_shared(smraw);
    __half* Ph  = (__half*)(smraw + A_PQ);
    const uint32_t PhU = sm_base + A_PQ;

    const int bh = blockIdx.y;
    const int b  = bh >> 4;
    const int h  = bh & 15;
    const int tid  = threadIdx.x;
    const int warp = tid >> 5;
    const int lane = tid & 31;
    const int lr = lane >> 2;
    const int lc = lane & 3;
    const int qt = gridDim.x - 1 - blockIdx.x;
    const int t0 = qt * 64;

    const int aRow = (lane & 15);
    const int aCol = (lane >> 4) * 8;
    const int bRow = ((lane >> 4) << 3) + (lane & 7);
    const int bCol = ((lane >> 3) & 1) * 8;

    // ---- stage Qh into Ph region ----
    #pragma unroll
    for (int i = 0; i < 4; i++) {
        int idx = tid + i * A_THREADS;      // 0..511 float4s
        int r = idx >> 3, c8 = (idx & 7) * 8;
        *(float4*)&Ph[r*72 + c8] =
            *(const float4*)(g_qh + ((size_t)bh*T_ + t0 + r)*D_ + c8);
    }
    __syncthreads();

    uint32_t qfh[4][4];
    #pragma unroll
    for (int ks = 0; ks < 4; ks++) {
        const uint32_t qo = (uint32_t)(((warp*16 + aRow) * 72) + 16*ks + aCol) * 2;
        ldsm_x4(qfh[ks], PhU + qo);
    }
    __syncthreads();

    float o[8][4];
    #pragma unroll
    for (int dt = 0; dt < 8; dt++)
        #pragma unroll
        for (int j = 0; j < 4; j++) o[dt][j] = 0.f;

    float m0 = -1e30f, m1 = -1e30f;
    float l0 = 0.f, l1 = 0.f;
    const float C2 = 0.125f * 1.44269504089f;

    const int rg0 = t0 + warp*16 + lr;
    const int rg1 = rg0 + 8;
    const int prow0 = (warp*16 + lr) * 72;
    const int prow1 = prow0 + 8*72;

    // ---- KV tile loader: Kh [kv][d]; Vh [d][kv]; 1024 16B chunks/stage ----
    auto issue_tile = [&](int stage, int j0) {
        const uint32_t st = sm_base + (uint32_t)stage * A_STAGE;
        #pragma unroll
        for (int i = 0; i < 8; i++) {
            int idx = tid + i * A_THREADS;   // 0..1023 16B chunks
            int sec = idx >> 9;              // 0:Kh 1:Vh
            int sub = idx & 511;
            int r   = sub >> 3;              // 0..63
            int c8  = (sub & 7) * 8;         // 0..56 halves
            const __half* src = (sec == 0)
                ? g_kh + ((size_t)bh*T_ + j0 + r)*D_ + c8
                : g_vh + ((size_t)bh*D_ + r)*T_ + j0 + c8;
            cp_async16(st + (uint32_t)(sec * 9216) + (uint32_t)(r*72 + c8)*2, src);
        }
        cp_async_commit();
    };

    const int ntiles = qt + 1;
    issue_tile(0, 0);

    for (int it = 0; it < ntiles; it++) {
        const int j0 = it * 64;
        if (it + 1 < ntiles) {
            issue_tile((it + 1) & 1, (it + 1) * 64);
            cp_async_wait<1>();
        } else {
            cp_async_wait<0>();
        }
        __syncthreads();

        const uint32_t KhU = sm_base + (uint32_t)((it & 1) * A_STAGE);
        const uint32_t VhU = KhU + 9216;

        // ---- S = Qh Kh^T  (1-pass) ----
        float s[8][4];
        #pragma unroll
        for (int nt = 0; nt < 8; nt++)
            #pragma unroll
            for (int j = 0; j < 4; j++) s[nt][j] = 0.f;

        #pragma unroll
        for (int ks = 0; ks < 4; ks++) {
            #pragma unroll
            for (int ntp = 0; ntp < 4; ntp++) {
                const uint32_t ko =
                    (uint32_t)(((ntp*16 + bRow) * 72) + 16*ks + bCol) * 2;
                uint32_t kh4[4];
                ldsm_x4(kh4, KhU + ko);
                #pragma unroll
                for (int half = 0; half < 2; half++) {
                    const int nt = 2*ntp + half;
                    mma_fp16(s[nt], qfh[ks], kh4[2*half], kh4[2*half+1]);
                }
            }
        }

        // ---- causal mask ----
        if (j0 + 63 > t0) {
            #pragma unroll
            for (int nt = 0; nt < 8; nt++) {
                int cg = j0 + nt*8 + 2*lc;
                if (cg     > rg0) s[nt][0] = -1e30f;
                if (cg + 1 > rg0) s[nt][1] = -1e30f;
                if (cg     > rg1) s[nt][2] = -1e30f;
                if (cg + 1 > rg1) s[nt][3] = -1e30f;
            }
        }

        // ---- online softmax ----
        float t0m = -1e30f, t1m = -1e30f;
        #pragma unroll
        for (int nt = 0; nt < 8; nt++) {
            t0m = fmaxf(t0m, fmaxf(s[nt][0], s[nt][1]));
            t1m = fmaxf(t1m, fmaxf(s[nt][2], s[nt][3]));
        }
        t0m = fmaxf(t0m, __shfl_xor_sync(0xffffffffu, t0m, 1));
        t0m = fmaxf(t0m, __shfl_xor_sync(0xffffffffu, t0m, 2));
        t1m = fmaxf(t1m, __shfl_xor_sync(0xffffffffu, t1m, 1));
        t1m = fmaxf(t1m, __shfl_xor_sync(0xffffffffu, t1m, 2));

        const float mn0 = fmaxf(m0, t0m);
        const float mn1 = fmaxf(m1, t1m);
        const float a0 = ex2f((m0 - mn0) * C2);
        const float a1 = ex2f((m1 - mn1) * C2);
        m0 = mn0; m1 = mn1;
        l0 *= a0; l1 *= a1;
        #pragma unroll
        for (int dt = 0; dt < 8; dt++) {
            o[dt][0] *= a0; o[dt][1] *= a0;
            o[dt][2] *= a1; o[dt][3] *= a1;
        }

        // ---- p -> fp16 (rounded); l accumulated from ROUNDED values ----
        #pragma unroll
        for (int nt = 0; nt < 8; nt++) {
            float p0 = ex2f((s[nt][0] - m0) * C2);
            float p1 = ex2f((s[nt][1] - m0) * C2);
            float p2 = ex2f((s[nt][2] - m1) * C2);
            float p3 = ex2f((s[nt][3] - m1) * C2);
            __half h0 = __float2half_rn(p0), h1 = __float2half_rn(p1);
            __half h2 = __float2half_rn(p2), h3 = __float2half_rn(p3);
            l0 += __half2float(h0) + __half2float(h1);
            l1 += __half2float(h2) + __half2float(h3);
            *(__half2*)&Ph[prow0 + nt*8 + 2*lc] = __halves2half2(h0, h1);
            *(__half2*)&Ph[prow1 + nt*8 + 2*lc] = __halves2half2(h2, h3);
        }
        __syncwarp();   // P rows are per-warp private

        // ---- O += Ph Vh  (1-pass) ----
        #pragma unroll
        for (int ks = 0; ks < 4; ks++) {
            uint32_t pah[4];
            const uint32_t po =
                (uint32_t)(((warp*16 + aRow) * 72) + 16*ks + aCol) * 2;
            ldsm_x4(pah, PhU + po);
            #pragma unroll
            for (int dtp = 0; dtp < 4; dtp++) {
                const uint32_t vo =
                    (uint32_t)(((dtp*16 + bRow) * 72) + 16*ks + bCol) * 2;
                uint32_t vh4[4];
                ldsm_x4(vh4, VhU + vo);
                #pragma unroll
                for (int half = 0; half < 2; half++) {
                    const int dt = 2*dtp + half;
                    mma_fp16(o[dt], pah, vh4[2*half], vh4[2*half+1]);
                }
            }
        }
        __syncthreads();
    }

    // ---- finalize ----
    l0 += __shfl_xor_sync(0xffffffffu, l0, 1);
    l0 += __shfl_xor_sync(0xffffffffu, l0, 2);
    l1 += __shfl_xor_sync(0xffffffffu, l1, 1);
    l1 += __shfl_xor_sync(0xffffffffu, l1, 2);
    const float inv0 = 1.f / l0;
    const float inv1 = 1.f / l1;

    float* out0 = out + ((size_t)(b*T_ + rg0))*C_ + h*D_;
    float* out1 = out + ((size_t)(b*T_ + rg1))*C_ + h*D_;
    #pragma unroll
    for (int dt = 0; dt < 8; dt++) {
        *(float2*)(out0 + dt*8 + 2*lc) = make_float2(o[dt][0]*inv0, o[dt][1]*inv0);
        *(float2*)(out1 + dt*8 + 2*lc) = make_float2(o[dt][2]*inv1, o[dt][3]*inv1);
    }
}

// ----------------------------------------------------------------------------
extern "C" void kernel_launch(void* const* d_in, const int* in_sizes, int n_in,
                              void* d_out, int out_size)
{
    const float* x_norm = (const float*)d_in[0];
    const float* xt_cur = (const float*)d_in[1];
    const float* W_attn = (const float*)d_in[2];
    const float* b_attn = (const float*)d_in[3];
    float* out = (float*)d_out;

    cudaFuncSetAttribute(gemm_qk_kernel,
                         cudaFuncAttributeMaxDynamicSharedMemorySize, GEMM_SMEM_BYTES);
    cudaFuncSetAttribute(attn_kernel,
                         cudaFuncAttributeMaxDynamicSharedMemorySize, ATTN_SMEM_BYTES);

    prep_x_kernel<<<(M_GEMM*K_GEMM/2)/256, 256>>>(x_norm);
    prep_w_kernel<<<dim3(N_GEMM/32, K_GEMM/32), dim3(32, 8)>>>(W_attn);
    prep_v_kernel<<<dim3(T_/32, D_/32, BH_), dim3(32, 8)>>>(xt_cur);

    dim3 g1(N_GEMM/128, M_GEMM/128);   // (16, 32)
    gemm_qk_kernel<<<g1, 256, GEMM_SMEM_BYTES>>>(b_attn);

    dim3 g2(T_/64, B_*H_);             // (32, 32)
    attn_kernel<<<g2, A_THREADS, ATTN_SMEM_BYTES>>>(out);
}

// round 16
// speedup vs baseline: 2.0284x; 1.2117x over previous
#include <cuda_runtime.h>
#include <cuda_fp16.h>
#include <cstdint>

// ============================================================================
// FactoredCausalSelfAttention  (B=2, T=2048, C=1024, H=16, D=64)
// Round 16: gemm cut to 1-pass pure fp16 (Xh @ Whi; W-lo dropped).
//           attn = round-15 exact (1-pass QK/PV).
//           Predicted rel_err ~5.3e-4.
// ============================================================================

#define B_   2
#define T_   2048
#define C_   1024
#define H_   16
#define D_   64
#define BH_  (B_*H_)
#define M_GEMM (B_*T_)      // 4096
#define N_GEMM (2*C_)       // 2048
#define K_GEMM (C_)         // 1024

// ---- device scratch ----
__device__ __align__(16) __half g_Xh [(size_t)M_GEMM*K_GEMM];
__device__ __align__(16) __half g_Whi[(size_t)N_GEMM*K_GEMM];  // [n][k]
__device__ __align__(16) __half g_qh [(size_t)BH_*T_*D_];      // [bh][t][d]
__device__ __align__(16) __half g_kh [(size_t)BH_*T_*D_];
__device__ __align__(16) __half g_vh [(size_t)BH_*D_*T_];      // [bh][d][t]

// ---------------------------------------------------------------- helpers ---
__device__ __forceinline__ void mma_fp16(float c[4], const uint32_t a[4],
                                         uint32_t b0, uint32_t b1)
{
    asm volatile(
        "mma.sync.aligned.m16n8k16.row.col.f32.f16.f16.f32 "
        "{%0,%1,%2,%3}, {%4,%5,%6,%7}, {%8,%9}, {%0,%1,%2,%3};\n"
        : "+f"(c[0]), "+f"(c[1]), "+f"(c[2]), "+f"(c[3])
        : "r"(a[0]), "r"(a[1]), "r"(a[2]), "r"(a[3]), "r"(b0), "r"(b1));
}

__device__ __forceinline__ void ldsm_x4(uint32_t r[4], uint32_t addr)
{
    asm volatile("ldmatrix.sync.aligned.m8n8.x4.shared.b16 {%0,%1,%2,%3}, [%4];"
                 : "=r"(r[0]), "=r"(r[1]), "=r"(r[2]), "=r"(r[3]) : "r"(addr));
}

__device__ __forceinline__ float ex2f(float x) {
    float y;
    asm("ex2.approx.f32 %0, %1;" : "=f"(y) : "f"(x));
    return y;
}

__device__ __forceinline__ void cp_async16(uint32_t smem_addr, const void* gptr) {
    asm volatile("cp.async.ca.shared.global [%0], [%1], 16;\n"
                 :: "r"(smem_addr), "l"(gptr));
}
__device__ __forceinline__ void cp_async_commit() {
    asm volatile("cp.async.commit_group;\n");
}
template<int N>
__device__ __forceinline__ void cp_async_wait() {
    asm volatile("cp.async.wait_group %0;\n" :: "n"(N));
}

// ----------------------------------------------------------------------------
// prep kernels
// ----------------------------------------------------------------------------
__global__ __launch_bounds__(256) void prep_x_kernel(const float* __restrict__ X)
{
    int i = blockIdx.x * 256 + threadIdx.x;
    float2 v = ((const float2*)X)[i];
    ((__half2*)g_Xh)[i] = __halves2half2(__float2half_rn(v.x), __float2half_rn(v.y));
}

__global__ __launch_bounds__(256) void prep_w_kernel(const float* __restrict__ W)
{
    __shared__ float t[32][33];
    const int bn = blockIdx.x, bk = blockIdx.y;
    const int tx = threadIdx.x, ty = threadIdx.y;
    #pragma unroll
    for (int j = 0; j < 4; j++)
        t[ty + 8*j][tx] = W[(size_t)(bk*32 + ty + 8*j) * N_GEMM + bn*32 + tx];
    __syncthreads();
    #pragma unroll
    for (int j = 0; j < 4; j++) {
        const int n = bn*32 + ty + 8*j;
        const int k = bk*32 + tx;
        g_Whi[(size_t)n * K_GEMM + k] = __float2half_rn(t[tx][ty + 8*j]);
    }
}

__global__ __launch_bounds__(256) void prep_v_kernel(const float* __restrict__ xt)
{
    __shared__ float t[32][33];
    const int bh = blockIdx.z;
    const int b = bh >> 4, h = bh & 15;
    const int tt = blockIdx.x * 32;
    const int dd = blockIdx.y * 32;
    const int tx = threadIdx.x, ty = threadIdx.y;
    #pragma unroll
    for (int j = 0; j < 4; j++)
        t[ty + 8*j][tx] = xt[(size_t)(b*T_ + tt + ty + 8*j) * C_ + h*D_ + dd + tx];
    __syncthreads();
    #pragma unroll
    for (int j = 0; j < 4; j++) {
        const int d = dd + ty + 8*j;
        g_vh[((size_t)bh*D_ + d) * T_ + tt + tx] = __float2half_rn(t[tx][ty + 8*j]);
    }
}

// ----------------------------------------------------------------------------
// GEMM (fp16 1-pass): qk ~= Xh @ Whi + bias -> scatter q/k fp16 (head-transp.)
// CTA 128x128, BK=32, 8 warps, 2-stage cp.async, ldmatrix frags.
// smem/stage: Ah[128][40], Bh[128][40] halves.
// ----------------------------------------------------------------------------
#define G_ARR (128*40)
#define G_STAGE (2*G_ARR)
#define GEMM_SMEM_BYTES (2*G_STAGE*2)   // 40960

__global__ __launch_bounds__(256, 2) void gemm_qk_kernel(const float* __restrict__ bias)
{
    extern __shared__ __half gsm[];
    const uint32_t smb = (uint32_t)__cvta_generic_to_shared(gsm);

    const int bx = blockIdx.x;
    const int by = blockIdx.y;
    const int tid = threadIdx.x;
    const int warp = tid >> 5;
    const int lane = tid & 31;
    const int lr = lane >> 2;
    const int lc = lane & 3;
    const int wm = warp >> 1;
    const int wn = warp & 1;

    const int aRow = (lane & 15);
    const int aCol = (lane >> 4) * 8;
    const int bRow = ((lane >> 4) << 3) + (lane & 7);
    const int bCol = ((lane >> 3) & 1) * 8;

    float c[2][8][4];
    #pragma unroll
    for (int mt = 0; mt < 2; mt++)
        #pragma unroll
        for (int nt = 0; nt < 8; nt++)
            #pragma unroll
            for (int j = 0; j < 4; j++) c[mt][nt][j] = 0.f;

    auto issue_stage = [&](int stage, int k0) {
        const uint32_t st = smb + (uint32_t)(stage * G_STAGE) * 2;
        #pragma unroll
        for (int i = 0; i < 4; i++) {
            int idx = tid + i * 256;          // 0..1023 16B chunks
            int sec = idx >> 9;               // 0:Ah 1:Bh
            int sub = idx & 511;
            int r   = sub >> 2;               // 0..127
            int c8  = (sub & 3) * 8;
            const __half* src = (sec == 0)
                ? g_Xh  + (size_t)(by*128 + r) * K_GEMM + k0 + c8
                : g_Whi + (size_t)(bx*128 + r) * K_GEMM + k0 + c8;
            cp_async16(st + (uint32_t)(sec * G_ARR + r * 40 + c8) * 2, src);
        }
        cp_async_commit();
    };

    issue_stage(0, 0);

    const int NIT = K_GEMM / 32;
    for (int it = 0; it < NIT; it++) {
        if (it + 1 < NIT) {
            issue_stage((it + 1) & 1, (it + 1) * 32);
            cp_async_wait<1>();
        } else {
            cp_async_wait<0>();
        }
        __syncthreads();

        const uint32_t Ah = smb + (uint32_t)((it & 1) * G_STAGE) * 2;
        const uint32_t Bh = Ah + G_ARR * 2;

        #pragma unroll
        for (int ks = 0; ks < 2; ks++) {
            uint32_t ah[2][4];
            #pragma unroll
            for (int mt = 0; mt < 2; mt++) {
                const uint32_t ao =
                    (uint32_t)(((wm*32 + mt*16 + aRow) * 40) + 16*ks + aCol) * 2;
                ldsm_x4(ah[mt], Ah + ao);
            }
            #pragma unroll
            for (int ntp = 0; ntp < 4; ntp++) {
                const uint32_t bo =
                    (uint32_t)(((wn*64 + ntp*16 + bRow) * 40) + 16*ks + bCol) * 2;
                uint32_t bh4[4];
                ldsm_x4(bh4, Bh + bo);
                #pragma unroll
                for (int half = 0; half < 2; half++)
                    #pragma unroll
                    for (int mt = 0; mt < 2; mt++)
                        mma_fp16(c[mt][2*ntp+half], ah[mt], bh4[2*half], bh4[2*half+1]);
            }
        }
        __syncthreads();
    }

    #pragma unroll
    for (int mt = 0; mt < 2; mt++) {
        #pragma unroll
        for (int rr = 0; rr < 2; rr++) {
            const int m = by*128 + wm*32 + mt*16 + rr*8 + lr;
            const int b = m >> 11;
            const int t = m & (T_ - 1);
            #pragma unroll
            for (int nt = 0; nt < 8; nt++) {
                const int n0 = bx*128 + wn*64 + nt*8 + 2*lc;
                const float v0 = c[mt][nt][rr*2 + 0] + bias[n0];
                const float v1 = c[mt][nt][rr*2 + 1] + bias[n0 + 1];
                const __half2 hv =
                    __halves2half2(__float2half_rn(v0), __float2half_rn(v1));
                if (n0 < C_) {
                    const int hh = n0 >> 6, d = n0 & 63;
                    *(__half2*)&g_qh[(((size_t)(b*H_ + hh)) * T_ + t) * D_ + d] = hv;
                } else {
                    const int n2 = n0 - C_;
                    const int hh = n2 >> 6, d = n2 & 63;
                    *(__half2*)&g_kh[(((size_t)(b*H_ + hh)) * T_ + t) * D_ + d] = hv;
                }
            }
        }
    }
}

// ----------------------------------------------------------------------------
// Flash attention (round-15 exact): 128 threads / 64 q-rows per CTA,
// 1-pass QK and PV, cp.async double-buffered KV, smem 46080B.
// ----------------------------------------------------------------------------
#define A_STAGE 18432
#define A_PQ    36864
#define ATTN_SMEM_BYTES 46080
#define A_THREADS 128

__global__ __launch_bounds__(A_THREADS) void attn_kernel(float* __restrict__ out)
{
    extern __shared__ char smraw[];
    const uint32_t sm_base = (uint32_t)__cvta_generic_to_shared(smraw);
    __half* Ph  = (__half*)(smraw + A_PQ);
    const uint32_t PhU = sm_base + A_PQ;

    const int bh = blockIdx.y;
    const int b  = bh >> 4;
    const int h  = bh & 15;
    const int tid  = threadIdx.x;
    const int warp = tid >> 5;
    const int lane = tid & 31;
    const int lr = lane >> 2;
    const int lc = lane & 3;
    const int qt = gridDim.x - 1 - blockIdx.x;
    const int t0 = qt * 64;

    const int aRow = (lane & 15);
    const int aCol = (lane >> 4) * 8;
    const int bRow = ((lane >> 4) << 3) + (lane & 7);
    const int bCol = ((lane >> 3) & 1) * 8;

    // ---- stage Qh into Ph region ----
    #pragma unroll
    for (int i = 0; i < 4; i++) {
        int idx = tid + i * A_THREADS;      // 0..511 float4s
        int r = idx >> 3, c8 = (idx & 7) * 8;
        *(float4*)&Ph[r*72 + c8] =
            *(const float4*)(g_qh + ((size_t)bh*T_ + t0 + r)*D_ + c8);
    }
    __syncthreads();

    uint32_t qfh[4][4];
    #pragma unroll
    for (int ks = 0; ks < 4; ks++) {
        const uint32_t qo = (uint32_t)(((warp*16 + aRow) * 72) + 16*ks + aCol) * 2;
        ldsm_x4(qfh[ks], PhU + qo);
    }
    __syncthreads();

    float o[8][4];
    #pragma unroll
    for (int dt = 0; dt < 8; dt++)
        #pragma unroll
        for (int j = 0; j < 4; j++) o[dt][j] = 0.f;

    float m0 = -1e30f, m1 = -1e30f;
    float l0 = 0.f, l1 = 0.f;
    const float C2 = 0.125f * 1.44269504089f;

    const int rg0 = t0 + warp*16 + lr;
    const int rg1 = rg0 + 8;
    const int prow0 = (warp*16 + lr) * 72;
    const int prow1 = prow0 + 8*72;

    auto issue_tile = [&](int stage, int j0) {
        const uint32_t st = sm_base + (uint32_t)stage * A_STAGE;
        #pragma unroll
        for (int i = 0; i < 8; i++) {
            int idx = tid + i * A_THREADS;   // 0..1023 16B chunks
            int sec = idx >> 9;              // 0:Kh 1:Vh
            int sub = idx & 511;
            int r   = sub >> 3;              // 0..63
            int c8  = (sub & 7) * 8;
            const __half* src = (sec == 0)
                ? g_kh + ((size_t)bh*T_ + j0 + r)*D_ + c8
                : g_vh + ((size_t)bh*D_ + r)*T_ + j0 + c8;
            cp_async16(st + (uint32_t)(sec * 9216) + (uint32_t)(r*72 + c8)*2, src);
        }
        cp_async_commit();
    };

    const int ntiles = qt + 1;
    issue_tile(0, 0);

    for (int it = 0; it < ntiles; it++) {
        const int j0 = it * 64;
        if (it + 1 < ntiles) {
            issue_tile((it + 1) & 1, (it + 1) * 64);
            cp_async_wait<1>();
        } else {
            cp_async_wait<0>();
        }
        __syncthreads();

        const uint32_t KhU = sm_base + (uint32_t)((it & 1) * A_STAGE);
        const uint32_t VhU = KhU + 9216;

        // ---- S = Qh Kh^T ----
        float s[8][4];
        #pragma unroll
        for (int nt = 0; nt < 8; nt++)
            #pragma unroll
            for (int j = 0; j < 4; j++) s[nt][j] = 0.f;

        #pragma unroll
        for (int ks = 0; ks < 4; ks++) {
            #pragma unroll
            for (int ntp = 0; ntp < 4; ntp++) {
                const uint32_t ko =
                    (uint32_t)(((ntp*16 + bRow) * 72) + 16*ks + bCol) * 2;
                uint32_t kh4[4];
                ldsm_x4(kh4, KhU + ko);
                #pragma unroll
                for (int half = 0; half < 2; half++) {
                    const int nt = 2*ntp + half;
                    mma_fp16(s[nt], qfh[ks], kh4[2*half], kh4[2*half+1]);
                }
            }
        }

        // ---- causal mask ----
        if (j0 + 63 > t0) {
            #pragma unroll
            for (int nt = 0; nt < 8; nt++) {
                int cg = j0 + nt*8 + 2*lc;
                if (cg     > rg0) s[nt][0] = -1e30f;
                if (cg + 1 > rg0) s[nt][1] = -1e30f;
                if (cg     > rg1) s[nt][2] = -1e30f;
                if (cg + 1 > rg1) s[nt][3] = -1e30f;
            }
        }

        // ---- online softmax ----
        float t0m = -1e30f, t1m = -1e30f;
        #pragma unroll
        for (int nt = 0; nt < 8; nt++) {
            t0m = fmaxf(t0m, fmaxf(s[nt][0], s[nt][1]));
            t1m = fmaxf(t1m, fmaxf(s[nt][2], s[nt][3]));
        }
        t0m = fmaxf(t0m, __shfl_xor_sync(0xffffffffu, t0m, 1));
        t0m = fmaxf(t0m, __shfl_xor_sync(0xffffffffu, t0m, 2));
        t1m = fmaxf(t1m, __shfl_xor_sync(0xffffffffu, t1m, 1));
        t1m = fmaxf(t1m, __shfl_xor_sync(0xffffffffu, t1m, 2));

        const float mn0 = fmaxf(m0, t0m);
        const float mn1 = fmaxf(m1, t1m);
        const float a0 = ex2f((m0 - mn0) * C2);
        const float a1 = ex2f((m1 - mn1) * C2);
        m0 = mn0; m1 = mn1;
        l0 *= a0; l1 *= a1;
        #pragma unroll
        for (int dt = 0; dt < 8; dt++) {
            o[dt][0] *= a0; o[dt][1] *= a0;
            o[dt][2] *= a1; o[dt][3] *= a1;
        }

        // ---- p -> fp16 (rounded); l accumulated from ROUNDED values ----
        #pragma unroll
        for (int nt = 0; nt < 8; nt++) {
            float p0 = ex2f((s[nt][0] - m0) * C2);
            float p1 = ex2f((s[nt][1] - m0) * C2);
            float p2 = ex2f((s[nt][2] - m1) * C2);
            float p3 = ex2f((s[nt][3] - m1) * C2);
            __half h0 = __float2half_rn(p0), h1 = __float2half_rn(p1);
            __half h2 = __float2half_rn(p2), h3 = __float2half_rn(p3);
            l0 += __half2float(h0) + __half2float(h1);
            l1 += __half2float(h2) + __half2float(h3);
            *(__half2*)&Ph[prow0 + nt*8 + 2*lc] = __halves2half2(h0, h1);
            *(__half2*)&Ph[prow1 + nt*8 + 2*lc] = __halves2half2(h2, h3);
        }
        __syncwarp();   // P rows are per-warp private

        // ---- O += Ph Vh ----
        #pragma unroll
        for (int ks = 0; ks < 4; ks++) {
            uint32_t pah[4];
            const uint32_t po =
                (uint32_t)(((warp*16 + aRow) * 72) + 16*ks + aCol) * 2;
            ldsm_x4(pah, PhU + po);
            #pragma unroll
            for (int dtp = 0; dtp < 4; dtp++) {
                const uint32_t vo =
                    (uint32_t)(((dtp*16 + bRow) * 72) + 16*ks + bCol) * 2;
                uint32_t vh4[4];
                ldsm_x4(vh4, VhU + vo);
                #pragma unroll
                for (int half = 0; half < 2; half++) {
                    const int dt = 2*dtp + half;
                    mma_fp16(o[dt], pah, vh4[2*half], vh4[2*half+1]);
                }
            }
        }
        __syncthreads();
    }

    // ---- finalize ----
    l0 += __shfl_xor_sync(0xffffffffu, l0, 1);
    l0 += __shfl_xor_sync(0xffffffffu, l0, 2);
    l1 += __shfl_xor_sync(0xffffffffu, l1, 1);
    l1 += __shfl_xor_sync(0xffffffffu, l1, 2);
    const float inv0 = 1.f / l0;
    const float inv1 = 1.f / l1;

    float* out0 = out + ((size_t)(b*T_ + rg0))*C_ + h*D_;
    float* out1 = out + ((size_t)(b*T_ + rg1))*C_ + h*D_;
    #pragma unroll
    for (int dt = 0; dt < 8; dt++) {
        *(float2*)(out0 + dt*8 + 2*lc) = make_float2(o[dt][0]*inv0, o[dt][1]*inv0);
        *(float2*)(out1 + dt*8 + 2*lc) = make_float2(o[dt][2]*inv1, o[dt][3]*inv1);
    }
}

// ----------------------------------------------------------------------------
extern "C" void kernel_launch(void* const* d_in, const int* in_sizes, int n_in,
                              void* d_out, int out_size)
{
    const float* x_norm = (const float*)d_in[0];
    const float* xt_cur = (const float*)d_in[1];
    const float* W_attn = (const float*)d_in[2];
    const float* b_attn = (const float*)d_in[3];
    float* out = (float*)d_out;

    cudaFuncSetAttribute(gemm_qk_kernel,
                         cudaFuncAttributeMaxDynamicSharedMemorySize, GEMM_SMEM_BYTES);
    cudaFuncSetAttribute(attn_kernel,
                         cudaFuncAttributeMaxDynamicSharedMemorySize, ATTN_SMEM_BYTES);

    prep_x_kernel<<<(M_GEMM*K_GEMM/2)/256, 256>>>(x_norm);
    prep_w_kernel<<<dim3(N_GEMM/32, K_GEMM/32), dim3(32, 8)>>>(W_attn);
    prep_v_kernel<<<dim3(T_/32, D_/32, BH_), dim3(32, 8)>>>(xt_cur);

    dim3 g1(N_GEMM/128, M_GEMM/128);   // (16, 32)
    gemm_qk_kernel<<<g1, 256, GEMM_SMEM_BYTES>>>(b_attn);

    dim3 g2(T_/64, B_*H_);             // (32, 32)
    attn_kernel<<<g2, A_THREADS, ATTN_SMEM_BYTES>>>(out);
}

// round 17
// speedup vs baseline: 2.1651x; 1.0674x over previous
#include <cuda_runtime.h>
#include <cuda_fp16.h>
#include <cstdint>

// ============================================================================
// FactoredCausalSelfAttention  (B=2, T=2048, C=1024, H=16, D=64)
// Round 17: halve iteration counts (sync/bubble overhead):
//   gemm BK 32->64 (16 iterations), attn KV-tile 64->128 (~8.7 tiles/CTA).
//   All matmuls 1-pass fp16 (round-16 precision).
// ============================================================================

#define B_   2
#define T_   2048
#define C_   1024
#define H_   16
#define D_   64
#define BH_  (B_*H_)
#define M_GEMM (B_*T_)      // 4096
#define N_GEMM (2*C_)       // 2048
#define K_GEMM (C_)         // 1024

// ---- device scratch ----
__device__ __align__(16) __half g_Xh [(size_t)M_GEMM*K_GEMM];
__device__ __align__(16) __half g_Whi[(size_t)N_GEMM*K_GEMM];  // [n][k]
__device__ __align__(16) __half g_qh [(size_t)BH_*T_*D_];      // [bh][t][d]
__device__ __align__(16) __half g_kh [(size_t)BH_*T_*D_];
__device__ __align__(16) __half g_vh [(size_t)BH_*D_*T_];      // [bh][d][t]

// ---------------------------------------------------------------- helpers ---
__device__ __forceinline__ void mma_fp16(float c[4], const uint32_t a[4],
                                         uint32_t b0, uint32_t b1)
{
    asm volatile(
        "mma.sync.aligned.m16n8k16.row.col.f32.f16.f16.f32 "
        "{%0,%1,%2,%3}, {%4,%5,%6,%7}, {%8,%9}, {%0,%1,%2,%3};\n"
        : "+f"(c[0]), "+f"(c[1]), "+f"(c[2]), "+f"(c[3])
        : "r"(a[0]), "r"(a[1]), "r"(a[2]), "r"(a[3]), "r"(b0), "r"(b1));
}

__device__ __forceinline__ void ldsm_x4(uint32_t r[4], uint32_t addr)
{
    asm volatile("ldmatrix.sync.aligned.m8n8.x4.shared.b16 {%0,%1,%2,%3}, [%4];"
                 : "=r"(r[0]), "=r"(r[1]), "=r"(r[2]), "=r"(r[3]) : "r"(addr));
}

__device__ __forceinline__ float ex2f(float x) {
    float y;
    asm("ex2.approx.f32 %0, %1;" : "=f"(y) : "f"(x));
    return y;
}

__device__ __forceinline__ void cp_async16(uint32_t smem_addr, const void* gptr) {
    asm volatile("cp.async.ca.shared.global [%0], [%1], 16;\n"
                 :: "r"(smem_addr), "l"(gptr));
}
__device__ __forceinline__ void cp_async_commit() {
    asm volatile("cp.async.commit_group;\n");
}
template<int N>
__device__ __forceinline__ void cp_async_wait() {
    asm volatile("cp.async.wait_group %0;\n" :: "n"(N));
}

// ----------------------------------------------------------------------------
// prep kernels (round-16 exact)
// ----------------------------------------------------------------------------
__global__ __launch_bounds__(256) void prep_x_kernel(const float* __restrict__ X)
{
    int i = blockIdx.x * 256 + threadIdx.x;
    float2 v = ((const float2*)X)[i];
    ((__half2*)g_Xh)[i] = __halves2half2(__float2half_rn(v.x), __float2half_rn(v.y));
}

__global__ __launch_bounds__(256) void prep_w_kernel(const float* __restrict__ W)
{
    __shared__ float t[32][33];
    const int bn = blockIdx.x, bk = blockIdx.y;
    const int tx = threadIdx.x, ty = threadIdx.y;
    #pragma unroll
    for (int j = 0; j < 4; j++)
        t[ty + 8*j][tx] = W[(size_t)(bk*32 + ty + 8*j) * N_GEMM + bn*32 + tx];
    __syncthreads();
    #pragma unroll
    for (int j = 0; j < 4; j++) {
        const int n = bn*32 + ty + 8*j;
        const int k = bk*32 + tx;
        g_Whi[(size_t)n * K_GEMM + k] = __float2half_rn(t[tx][ty + 8*j]);
    }
}

__global__ __launch_bounds__(256) void prep_v_kernel(const float* __restrict__ xt)
{
    __shared__ float t[32][33];
    const int bh = blockIdx.z;
    const int b = bh >> 4, h = bh & 15;
    const int tt = blockIdx.x * 32;
    const int dd = blockIdx.y * 32;
    const int tx = threadIdx.x, ty = threadIdx.y;
    #pragma unroll
    for (int j = 0; j < 4; j++)
        t[ty + 8*j][tx] = xt[(size_t)(b*T_ + tt + ty + 8*j) * C_ + h*D_ + dd + tx];
    __syncthreads();
    #pragma unroll
    for (int j = 0; j < 4; j++) {
        const int d = dd + ty + 8*j;
        g_vh[((size_t)bh*D_ + d) * T_ + tt + tx] = __float2half_rn(t[tx][ty + 8*j]);
    }
}

// ----------------------------------------------------------------------------
// GEMM (fp16 1-pass, BK=64): qk ~= Xh @ Whi + bias -> scatter q/k fp16
// CTA 128x128, 16 iterations, 2-stage cp.async, ldmatrix frags.
// smem/stage: Ah[128][72], Bh[128][72] halves (36864B); x2 stages = 73728B.
// ----------------------------------------------------------------------------
#define G_ARR (128*72)
#define G_STAGE (2*G_ARR)
#define GEMM_SMEM_BYTES (2*G_STAGE*2)   // 73728

__global__ __launch_bounds__(256, 2) void gemm_qk_kernel(const float* __restrict__ bias)
{
    extern __shared__ __half gsm[];
    const uint32_t smb = (uint32_t)__cvta_generic_to_shared(gsm);

    const int bx = blockIdx.x;
    const int by = blockIdx.y;
    const int tid = threadIdx.x;
    const int warp = tid >> 5;
    const int lane = tid & 31;
    const int lr = lane >> 2;
    const int lc = lane & 3;
    const int wm = warp >> 1;
    const int wn = warp & 1;

    const int aRow = (lane & 15);
    const int aCol = (lane >> 4) * 8;
    const int bRow = ((lane >> 4) << 3) + (lane & 7);
    const int bCol = ((lane >> 3) & 1) * 8;

    float c[2][8][4];
    #pragma unroll
    for (int mt = 0; mt < 2; mt++)
        #pragma unroll
        for (int nt = 0; nt < 8; nt++)
            #pragma unroll
            for (int j = 0; j < 4; j++) c[mt][nt][j] = 0.f;

    auto issue_stage = [&](int stage, int k0) {
        const uint32_t st = smb + (uint32_t)(stage * G_STAGE) * 2;
        #pragma unroll
        for (int i = 0; i < 8; i++) {
            int idx = tid + i * 256;          // 0..2047 16B chunks
            int sec = idx >> 10;              // 0:Ah 1:Bh
            int sub = idx & 1023;
            int r   = sub >> 3;               // 0..127
            int c8  = (sub & 7) * 8;          // 0..56
            const __half* src = (sec == 0)
                ? g_Xh  + (size_t)(by*128 + r) * K_GEMM + k0 + c8
                : g_Whi + (size_t)(bx*128 + r) * K_GEMM + k0 + c8;
            cp_async16(st + (uint32_t)(sec * G_ARR + r * 72 + c8) * 2, src);
        }
        cp_async_commit();
    };

    issue_stage(0, 0);

    const int NIT = K_GEMM / 64;   // 16
    for (int it = 0; it < NIT; it++) {
        if (it + 1 < NIT) {
            issue_stage((it + 1) & 1, (it + 1) * 64);
            cp_async_wait<1>();
        } else {
            cp_async_wait<0>();
        }
        __syncthreads();

        const uint32_t Ah = smb + (uint32_t)((it & 1) * G_STAGE) * 2;
        const uint32_t Bh = Ah + G_ARR * 2;

        #pragma unroll
        for (int ks = 0; ks < 4; ks++) {
            uint32_t ah[2][4];
            #pragma unroll
            for (int mt = 0; mt < 2; mt++) {
                const uint32_t ao =
                    (uint32_t)(((wm*32 + mt*16 + aRow) * 72) + 16*ks + aCol) * 2;
                ldsm_x4(ah[mt], Ah + ao);
            }
            #pragma unroll
            for (int ntp = 0; ntp < 4; ntp++) {
                const uint32_t bo =
                    (uint32_t)(((wn*64 + ntp*16 + bRow) * 72) + 16*ks + bCol) * 2;
                uint32_t bh4[4];
                ldsm_x4(bh4, Bh + bo);
                #pragma unroll
                for (int half = 0; half < 2; half++)
                    #pragma unroll
                    for (int mt = 0; mt < 2; mt++)
                        mma_fp16(c[mt][2*ntp+half], ah[mt], bh4[2*half], bh4[2*half+1]);
            }
        }
        __syncthreads();
    }

    #pragma unroll
    for (int mt = 0; mt < 2; mt++) {
        #pragma unroll
        for (int rr = 0; rr < 2; rr++) {
            const int m = by*128 + wm*32 + mt*16 + rr*8 + lr;
            const int b = m >> 11;
            const int t = m & (T_ - 1);
            #pragma unroll
            for (int nt = 0; nt < 8; nt++) {
                const int n0 = bx*128 + wn*64 + nt*8 + 2*lc;
                const float v0 = c[mt][nt][rr*2 + 0] + bias[n0];
                const float v1 = c[mt][nt][rr*2 + 1] + bias[n0 + 1];
                const __half2 hv =
                    __halves2half2(__float2half_rn(v0), __float2half_rn(v1));
                if (n0 < C_) {
                    const int hh = n0 >> 6, d = n0 & 63;
                    *(__half2*)&g_qh[(((size_t)(b*H_ + hh)) * T_ + t) * D_ + d] = hv;
                } else {
                    const int n2 = n0 - C_;
                    const int hh = n2 >> 6, d = n2 & 63;
                    *(__half2*)&g_kh[(((size_t)(b*H_ + hh)) * T_ + t) * D_ + d] = hv;
                }
            }
        }
    }
}

// ----------------------------------------------------------------------------
// Flash attention: 128 threads / 64 q-rows per CTA, KV tiles of 128.
// 1-pass QK and PV. smem per CTA:
//   stage s @ s*35840: Kh[128][72] @ 0 (18432B), Vh[64][136] @ 18432 (17408B)
//   Ph[64][136] @ 71680 (17408B; Q staging aliases it) -> total 89088B
// 2 CTAs/SM.
// ----------------------------------------------------------------------------
#define A_STAGE 35840
#define A_VOFF  18432
#define A_PQ    71680
#define ATTN_SMEM_BYTES 89088
#define A_THREADS 128

__global__ __launch_bounds__(A_THREADS) void attn_kernel(float* __restrict__ out)
{
    extern __shared__ char smraw[];
    const uint32_t sm_base = (uint32_t)__cvta_generic_to_shared(smraw);
    __half* Ph  = (__half*)(smraw + A_PQ);
    const uint32_t PhU = sm_base + A_PQ;

    const int bh = blockIdx.y;
    const int b  = bh >> 4;
    const int h  = bh & 15;
    const int tid  = threadIdx.x;
    const int warp = tid >> 5;
    const int lane = tid & 31;
    const int lr = lane >> 2;
    const int lc = lane & 3;
    const int qt = gridDim.x - 1 - blockIdx.x;
    const int t0 = qt * 64;

    const int aRow = (lane & 15);
    const int aCol = (lane >> 4) * 8;
    const int bRow = ((lane >> 4) << 3) + (lane & 7);
    const int bCol = ((lane >> 3) & 1) * 8;

    // ---- stage Qh into Ph region (stride 136) ----
    #pragma unroll
    for (int i = 0; i < 4; i++) {
        int idx = tid + i * A_THREADS;      // 0..511 float4s
        int r = idx >> 3, c8 = (idx & 7) * 8;
        *(float4*)&Ph[r*136 + c8] =
            *(const float4*)(g_qh + ((size_t)bh*T_ + t0 + r)*D_ + c8);
    }
    __syncthreads();

    uint32_t qfh[4][4];
    #pragma unroll
    for (int ks = 0; ks < 4; ks++) {
        const uint32_t qo = (uint32_t)(((warp*16 + aRow) * 136) + 16*ks + aCol) * 2;
        ldsm_x4(qfh[ks], PhU + qo);
    }
    __syncthreads();

    float o[8][4];
    #pragma unroll
    for (int dt = 0; dt < 8; dt++)
        #pragma unroll
        for (int j = 0; j < 4; j++) o[dt][j] = 0.f;

    float m0 = -1e30f, m1 = -1e30f;
    float l0 = 0.f, l1 = 0.f;
    const float C2 = 0.125f * 1.44269504089f;

    const int rg0 = t0 + warp*16 + lr;
    const int rg1 = rg0 + 8;
    const int prow0 = (warp*16 + lr) * 136;
    const int prow1 = prow0 + 8*136;

    // ---- KV tile loader: Kh [128 kv][64 d] stride 72; Vh [64 d][128 kv] 136 ----
    auto issue_tile = [&](int stage, int j0) {
        const uint32_t st = sm_base + (uint32_t)stage * A_STAGE;
        #pragma unroll
        for (int i = 0; i < 16; i++) {
            int idx = tid + i * A_THREADS;   // 0..2047 16B chunks
            if (idx < 1024) {                // Kh: 128 rows x 8 chunks
                int r  = idx >> 3;
                int c8 = (idx & 7) * 8;
                cp_async16(st + (uint32_t)(r*72 + c8)*2,
                           g_kh + ((size_t)bh*T_ + j0 + r)*D_ + c8);
            } else {                         // Vh: 64 rows x 16 chunks
                int sub = idx - 1024;
                int r   = sub >> 4;
                int c16 = (sub & 15) * 8;
                cp_async16(st + A_VOFF + (uint32_t)(r*136 + c16)*2,
                           g_vh + ((size_t)bh*D_ + r)*T_ + j0 + c16);
            }
        }
        cp_async_commit();
    };

    const int ntiles = qt/2 + 1;
    issue_tile(0, 0);

    for (int it = 0; it < ntiles; it++) {
        const int j0 = it * 128;
        if (it + 1 < ntiles) {
            issue_tile((it + 1) & 1, (it + 1) * 128);
            cp_async_wait<1>();
        } else {
            cp_async_wait<0>();
        }
        __syncthreads();

        const uint32_t KhU = sm_base + (uint32_t)((it & 1) * A_STAGE);
        const uint32_t VhU = KhU + A_VOFF;

        // ---- S = Qh Kh^T  (64 x 128 per CTA) ----
        float s[16][4];
        #pragma unroll
        for (int nt = 0; nt < 16; nt++)
            #pragma unroll
            for (int j = 0; j < 4; j++) s[nt][j] = 0.f;

        #pragma unroll
        for (int ks = 0; ks < 4; ks++) {
            #pragma unroll
            for (int ntp = 0; ntp < 8; ntp++) {
                const uint32_t ko =
                    (uint32_t)(((ntp*16 + bRow) * 72) + 16*ks + bCol) * 2;
                uint32_t kh4[4];
                ldsm_x4(kh4, KhU + ko);
                #pragma unroll
                for (int half = 0; half < 2; half++) {
                    const int nt = 2*ntp + half;
                    mma_fp16(s[nt], qfh[ks], kh4[2*half], kh4[2*half+1]);
                }
            }
        }

        // ---- causal mask ----
        if (j0 + 127 > t0) {
            #pragma unroll
            for (int nt = 0; nt < 16; nt++) {
                int cg = j0 + nt*8 + 2*lc;
                if (cg     > rg0) s[nt][0] = -1e30f;
                if (cg + 1 > rg0) s[nt][1] = -1e30f;
                if (cg     > rg1) s[nt][2] = -1e30f;
                if (cg + 1 > rg1) s[nt][3] = -1e30f;
            }
        }

        // ---- online softmax ----
        float t0m = -1e30f, t1m = -1e30f;
        #pragma unroll
        for (int nt = 0; nt < 16; nt++) {
            t0m = fmaxf(t0m, fmaxf(s[nt][0], s[nt][1]));
            t1m = fmaxf(t1m, fmaxf(s[nt][2], s[nt][3]));
        }
        t0m = fmaxf(t0m, __shfl_xor_sync(0xffffffffu, t0m, 1));
        t0m = fmaxf(t0m, __shfl_xor_sync(0xffffffffu, t0m, 2));
        t1m = fmaxf(t1m, __shfl_xor_sync(0xffffffffu, t1m, 1));
        t1m = fmaxf(t1m, __shfl_xor_sync(0xffffffffu, t1m, 2));

        const float mn0 = fmaxf(m0, t0m);
        const float mn1 = fmaxf(m1, t1m);
        const float a0 = ex2f((m0 - mn0) * C2);
        const float a1 = ex2f((m1 - mn1) * C2);
        m0 = mn0; m1 = mn1;
        l0 *= a0; l1 *= a1;
        #pragma unroll
        for (int dt = 0; dt < 8; dt++) {
            o[dt][0] *= a0; o[dt][1] *= a0;
            o[dt][2] *= a1; o[dt][3] *= a1;
        }

        // ---- p -> fp16 (rounded); l accumulated from ROUNDED values ----
        #pragma unroll
        for (int nt = 0; nt < 16; nt++) {
            float p0 = ex2f((s[nt][0] - m0) * C2);
            float p1 = ex2f((s[nt][1] - m0) * C2);
            float p2 = ex2f((s[nt][2] - m1) * C2);
            float p3 = ex2f((s[nt][3] - m1) * C2);
            __half h0 = __float2half_rn(p0), h1 = __float2half_rn(p1);
            __half h2 = __float2half_rn(p2), h3 = __float2half_rn(p3);
            l0 += __half2float(h0) + __half2float(h1);
            l1 += __half2float(h2) + __half2float(h3);
            *(__half2*)&Ph[prow0 + nt*8 + 2*lc] = __halves2half2(h0, h1);
            *(__half2*)&Ph[prow1 + nt*8 + 2*lc] = __halves2half2(h2, h3);
        }
        __syncwarp();   // P rows are per-warp private

        // ---- O += Ph Vh  (contraction over 128 kv) ----
        #pragma unroll
        for (int ks = 0; ks < 8; ks++) {
            uint32_t pah[4];
            const uint32_t po =
                (uint32_t)(((warp*16 + aRow) * 136) + 16*ks + aCol) * 2;
            ldsm_x4(pah, PhU + po);
            #pragma unroll
            for (int dtp = 0; dtp < 4; dtp++) {
                const uint32_t vo =
                    (uint32_t)(((dtp*16 + bRow) * 136) + 16*ks + bCol) * 2;
                uint32_t vh4[4];
                ldsm_x4(vh4, VhU + vo);
                #pragma unroll
                for (int half = 0; half < 2; half++) {
                    const int dt = 2*dtp + half;
                    mma_fp16(o[dt], pah, vh4[2*half], vh4[2*half+1]);
                }
            }
        }
        __syncthreads();
    }

    // ---- finalize ----
    l0 += __shfl_xor_sync(0xffffffffu, l0, 1);
    l0 += __shfl_xor_sync(0xffffffffu, l0, 2);
    l1 += __shfl_xor_sync(0xffffffffu, l1, 1);
    l1 += __shfl_xor_sync(0xffffffffu, l1, 2);
    const float inv0 = 1.f / l0;
    const float inv1 = 1.f / l1;

    float* out0 = out + ((size_t)(b*T_ + rg0))*C_ + h*D_;
    float* out1 = out + ((size_t)(b*T_ + rg1))*C_ + h*D_;
    #pragma unroll
    for (int dt = 0; dt < 8; dt++) {
        *(float2*)(out0 + dt*8 + 2*lc) = make_float2(o[dt][0]*inv0, o[dt][1]*inv0);
        *(float2*)(out1 + dt*8 + 2*lc) = make_float2(o[dt][2]*inv1, o[dt][3]*inv1);
    }
}

// ----------------------------------------------------------------------------
extern "C" void kernel_launch(void* const* d_in, const int* in_sizes, int n_in,
                              void* d_out, int out_size)
{
    const float* x_norm = (const float*)d_in[0];
    const float* xt_cur = (const float*)d_in[1];
    const float* W_attn = (const float*)d_in[2];
    const float* b_attn = (const float*)d_in[3];
    float* out = (float*)d_out;

    cudaFuncSetAttribute(gemm_qk_kernel,
                         cudaFuncAttributeMaxDynamicSharedMemorySize, GEMM_SMEM_BYTES);
    cudaFuncSetAttribute(attn_kernel,
                         cudaFuncAttributeMaxDynamicSharedMemorySize, ATTN_SMEM_BYTES);

    prep_x_kernel<<<(M_GEMM*K_GEMM/2)/256, 256>>>(x_norm);
    prep_w_kernel<<<dim3(N_GEMM/32, K_GEMM/32), dim3(32, 8)>>>(W_attn);
    prep_v_kernel<<<dim3(T_/32, D_/32, BH_), dim3(32, 8)>>>(xt_cur);

    dim3 g1(N_GEMM/128, M_GEMM/128);   // (16, 32)
    gemm_qk_kernel<<<g1, 256, GEMM_SMEM_BYTES>>>(b_attn);

    dim3 g2(T_/64, B_*H_);             // (32, 32)
    attn_kernel<<<g2, A_THREADS, ATTN_SMEM_BYTES>>>(out);
}